// round 6
// baseline (speedup 1.0000x reference)
#include <cuda_runtime.h>
#include <math.h>

#define NMAX 100000
#define EMAX 1600000
#define BN_EPS 1e-5f

// ---------------- device scratch ----------------
__device__ int   g_is64;
__device__ int   g_deg[NMAX];
__device__ float g_dinv[NMAX];
__device__ int   g_rowptr[NMAX + 1];
__device__ int   g_cursor[NMAX];
__device__ unsigned long long g_edge[EMAX + NMAX];   // low32 = col, high32 = weight bits
__device__ float g_h0[(size_t)NMAX * 64];
__device__ float g_t [(size_t)NMAX * 128];
__device__ float g_h [(size_t)NMAX * 128];

// ---------------- packed f32x2 helpers ----------------
__device__ __forceinline__ unsigned long long pk2(float x, float y) {
    unsigned long long r;
    asm("mov.b64 %0, {%1, %2};" : "=l"(r) : "f"(x), "f"(y));
    return r;
}
__device__ __forceinline__ void upk2(float& x, float& y, unsigned long long v) {
    asm("mov.b64 {%0, %1}, %2;" : "=f"(x), "=f"(y) : "l"(v));
}
#define FMA2(acc, a, b) asm("fma.rn.f32x2 %0, %1, %2, %0;" : "+l"(acc) : "l"(a), "l"(b))

// ---------------- preprocessing ----------------

__global__ void k_init(const void* eidx, int n) {
    int i = blockIdx.x * blockDim.x + threadIdx.x;
    if (i < n) g_deg[i] = 0;
    if (i == 0) {
        const unsigned int* p = (const unsigned int*)eidx;
        int is64 = 1;
        for (int k = 0; k < 32; k++)
            if (p[2 * k + 1] != 0u) { is64 = 0; break; }
        g_is64 = is64;
    }
}

// count in-degree reading dst directly from edge_index
__global__ void k_count(const void* eidx, int E) {
    int i = blockIdx.x * blockDim.x + threadIdx.x;
    if (i >= E) return;
    int d;
    if (g_is64) d = (int)((const long long*)eidx)[(size_t)E + i];
    else        d = ((const int*)eidx)[E + i];
    atomicAdd(&g_deg[d], 1);
}

// single-block: exclusive scan of (deg[i]+1) -> rowptr, plus per-node work:
// dinv, cursor init, self-loop placed in last CSR slot of each row.
__global__ void k_scan_node(int n) {
    __shared__ int s[1024];
    int t = threadIdx.x;
    int chunk = (n + 1023) / 1024;
    int lo = t * chunk;
    int hi = lo + chunk; if (hi > n) hi = n;
    int sum = 0;
    if (lo < n) for (int i = lo; i < hi; i++) sum += g_deg[i] + 1;
    s[t] = sum;
    __syncthreads();
    for (int d = 1; d < 1024; d <<= 1) {
        int v = 0;
        if (t >= d) v = s[t - d];
        __syncthreads();
        s[t] += v;
        __syncthreads();
    }
    int off = (t == 0) ? 0 : s[t - 1];
    if (lo < n) {
        int run = off;
        for (int i = lo; i < hi; i++) {
            int deg = g_deg[i];
            g_rowptr[i] = run;
            g_cursor[i] = run;
            float di = rsqrtf((float)(deg + 1));
            g_dinv[i] = di;
            g_edge[run + deg] = ((unsigned long long)__float_as_uint(di * di) << 32) |
                                (unsigned long long)(unsigned int)i;
            run += deg + 1;
        }
    }
    if (t == 1023) g_rowptr[n] = s[1023];
}

// scatter edges into CSR slots reading src/dst directly from edge_index
__global__ void k_fill_edges(const void* eidx, int E) {
    int e = blockIdx.x * blockDim.x + threadIdx.x;
    if (e >= E) return;
    int s, d;
    if (g_is64) {
        const long long* p = (const long long*)eidx;
        s = (int)p[e];
        d = (int)p[(size_t)E + e];
    } else {
        const int* p = (const int*)eidx;
        s = p[e];
        d = p[E + e];
    }
    int pos = atomicAdd(&g_cursor[d], 1);
    float w = g_dinv[s] * g_dinv[d];
    g_edge[pos] = ((unsigned long long)__float_as_uint(w) << 32) |
                  (unsigned long long)(unsigned int)s;
}

// ---------------- GEMM: C[n,FOUT] = A[n,FIN] @ W[FIN,FOUT] (+ epilogue) -------
// (round-2 known-good form) EPI: 0 = none, 1 = bias+relu, 2 = bias+bn+relu
template <int FIN, int FOUT, int EPI>
__global__ __launch_bounds__(256) void k_gemm(
    const float* __restrict__ A, const float* __restrict__ W,
    const float* __restrict__ bias,
    const float* __restrict__ gm, const float* __restrict__ bt,
    const float* __restrict__ mn, const float* __restrict__ vr,
    float* __restrict__ C, int n)
{
    constexpr int BM = 64, KC = 32;
    constexpr int NTC = FOUT / 4;        // thread cols (4 outputs each)
    constexpr int NTR = 256 / NTC;       // thread rows
    constexpr int TM  = BM / NTR;        // rows per thread

    __shared__ unsigned long long As2[BM][KC + 1];   // {a,a} duplicated pairs
    __shared__ float Ws[KC][FOUT];

    int tid = threadIdx.x;
    int rowBase = blockIdx.x * BM;
    int colT = tid % NTC;
    int rowT = tid / NTC;
    int col0 = colT * 4;

    unsigned long long acc2[TM][2];
    #pragma unroll
    for (int r = 0; r < TM; r++) { acc2[r][0] = 0ull; acc2[r][1] = 0ull; }

    for (int k0 = 0; k0 < FIN; k0 += KC) {
        #pragma unroll
        for (int j = 0; j < 2; j++) {
            int idx = tid + 256 * j;
            int r = idx >> 3, c4 = idx & 7;
            int grow = rowBase + r;
            float4 v = make_float4(0.f, 0.f, 0.f, 0.f);
            if (grow < n)
                v = *reinterpret_cast<const float4*>(&A[(size_t)grow * FIN + k0 + c4 * 4]);
            As2[r][c4 * 4 + 0] = pk2(v.x, v.x);
            As2[r][c4 * 4 + 1] = pk2(v.y, v.y);
            As2[r][c4 * 4 + 2] = pk2(v.z, v.z);
            As2[r][c4 * 4 + 3] = pk2(v.w, v.w);
        }
        constexpr int WV = KC * FOUT / 4;
        #pragma unroll
        for (int j = 0; j < WV / 256; j++) {
            int idx = tid + 256 * j;
            int r = idx / (FOUT / 4), c4 = idx % (FOUT / 4);
            float4 v = *reinterpret_cast<const float4*>(&W[(size_t)(k0 + r) * FOUT + c4 * 4]);
            *reinterpret_cast<float4*>(&Ws[r][c4 * 4]) = v;
        }
        __syncthreads();
        #pragma unroll
        for (int kk = 0; kk < KC; kk++) {
            ulonglong2 wv = *reinterpret_cast<const ulonglong2*>(&Ws[kk][col0]);
            #pragma unroll
            for (int r = 0; r < TM; r++) {
                unsigned long long a2 = As2[rowT * TM + r][kk];
                FMA2(acc2[r][0], a2, wv.x);
                FMA2(acc2[r][1], a2, wv.y);
            }
        }
        __syncthreads();
    }

    float s[4] = {1.f, 1.f, 1.f, 1.f};
    float t[4] = {0.f, 0.f, 0.f, 0.f};
    if constexpr (EPI == 1) {
        #pragma unroll
        for (int c = 0; c < 4; c++) t[c] = bias[col0 + c];
    } else if constexpr (EPI == 2) {
        #pragma unroll
        for (int c = 0; c < 4; c++) {
            int cc = col0 + c;
            float sc = gm[cc] * rsqrtf(vr[cc] + BN_EPS);
            s[c] = sc;
            t[c] = (bias[cc] - mn[cc]) * sc + bt[cc];
        }
    }

    #pragma unroll
    for (int r = 0; r < TM; r++) {
        int grow = rowBase + rowT * TM + r;
        if (grow >= n) continue;
        float v0, v1, v2, v3;
        upk2(v0, v1, acc2[r][0]);
        upk2(v2, v3, acc2[r][1]);
        v0 = v0 * s[0] + t[0];
        v1 = v1 * s[1] + t[1];
        v2 = v2 * s[2] + t[2];
        v3 = v3 * s[3] + t[3];
        if constexpr (EPI != 0) {
            v0 = fmaxf(v0, 0.f); v1 = fmaxf(v1, 0.f);
            v2 = fmaxf(v2, 0.f); v3 = fmaxf(v3, 0.f);
        }
        float4 st; st.x = v0; st.y = v1; st.z = v2; st.w = v3;
        *reinterpret_cast<float4*>(&C[(size_t)grow * FOUT + col0]) = st;
    }
}

// ---------------- aggregation: O[i] = sum_e w[e]*H[col[e]] ----------------
// 2 feats per thread (FFMA2), FW/2 threads per node, 128-thread blocks,
// unroll-4 with 4 accumulators (moderate MLP; avoids L1tex queue pile-up).
// EPI: 0 = none; 2 = bn+relu then fused (h @ w_out + b_out -> log_softmax).
template <int FW, int EPI>
__global__ __launch_bounds__(128) void k_agg(
    const float* __restrict__ H, float* __restrict__ O,
    const float* __restrict__ b,
    const float* __restrict__ gm, const float* __restrict__ bt,
    const float* __restrict__ mn, const float* __restrict__ vr,
    const float* __restrict__ Wo, const float* __restrict__ bo,
    float* __restrict__ out, int n)
{
    constexpr int TPN = FW / 2;            // threads per node
    constexpr int NPB = 128 / TPN;         // nodes per block

    __shared__ float wsT[8 * 64];          // [c][f]  (EPI==2 only)
    __shared__ float bsh[8];
    if constexpr (EPI == 2) {
        int tid = threadIdx.y * TPN + threadIdx.x;
        for (int idx = tid; idx < 512; idx += 128) {
            int f = idx >> 3, c = idx & 7;
            wsT[c * 64 + f] = Wo[idx];
        }
        if (tid < 8) bsh[tid] = bo[tid];
        __syncthreads();
    }

    int node = blockIdx.x * NPB + threadIdx.y;
    if (node >= n) return;
    int f2 = threadIdx.x;                  // feature-pair index

    int s = g_rowptr[node], e = g_rowptr[node + 1];
    unsigned long long acc0 = 0ull, acc1 = 0ull, acc2_ = 0ull, acc3 = 0ull;

    int p = s;
    for (; p + 4 <= e; p += 4) {
        unsigned long long e0 = g_edge[p];
        unsigned long long e1 = g_edge[p + 1];
        unsigned long long e2 = g_edge[p + 2];
        unsigned long long e3 = g_edge[p + 3];
        unsigned long long h0 = *reinterpret_cast<const unsigned long long*>(
            &H[(size_t)(unsigned int)e0 * FW + 2 * f2]);
        unsigned long long h1 = *reinterpret_cast<const unsigned long long*>(
            &H[(size_t)(unsigned int)e1 * FW + 2 * f2]);
        unsigned long long h2 = *reinterpret_cast<const unsigned long long*>(
            &H[(size_t)(unsigned int)e2 * FW + 2 * f2]);
        unsigned long long h3 = *reinterpret_cast<const unsigned long long*>(
            &H[(size_t)(unsigned int)e3 * FW + 2 * f2]);
        float w0 = __uint_as_float((unsigned int)(e0 >> 32));
        float w1 = __uint_as_float((unsigned int)(e1 >> 32));
        float w2 = __uint_as_float((unsigned int)(e2 >> 32));
        float w3 = __uint_as_float((unsigned int)(e3 >> 32));
        unsigned long long wd0 = pk2(w0, w0);
        unsigned long long wd1 = pk2(w1, w1);
        unsigned long long wd2 = pk2(w2, w2);
        unsigned long long wd3 = pk2(w3, w3);
        FMA2(acc0, wd0, h0);
        FMA2(acc1, wd1, h1);
        FMA2(acc2_, wd2, h2);
        FMA2(acc3, wd3, h3);
    }
    for (; p < e; ++p) {
        unsigned long long ed = g_edge[p];
        float w = __uint_as_float((unsigned int)(ed >> 32));
        unsigned long long wd = pk2(w, w);
        unsigned long long hv = *reinterpret_cast<const unsigned long long*>(
            &H[(size_t)(unsigned int)ed * FW + 2 * f2]);
        FMA2(acc0, wd, hv);
    }

    float a0, a1, t0, t1;
    upk2(a0, a1, acc0);
    upk2(t0, t1, acc1);  a0 += t0; a1 += t1;
    upk2(t0, t1, acc2_); a0 += t0; a1 += t1;
    upk2(t0, t1, acc3);  a0 += t0; a1 += t1;

    int f = 2 * f2;
    if constexpr (EPI == 2) {
        // bn + relu
        float s0 = gm[f] * rsqrtf(vr[f] + BN_EPS);
        float s1 = gm[f + 1] * rsqrtf(vr[f + 1] + BN_EPS);
        float v0 = fmaxf((a0 + b[f] - mn[f]) * s0 + bt[f], 0.f);
        float v1 = fmaxf((a1 + b[f + 1] - mn[f + 1]) * s1 + bt[f + 1], 0.f);
        // fused 64x8 GEMM via warp reduction (TPN==32: one warp per node)
        float l[8];
        #pragma unroll
        for (int c = 0; c < 8; c++) {
            float pr = v0 * wsT[c * 64 + f] + v1 * wsT[c * 64 + f + 1];
            #pragma unroll
            for (int off = 16; off; off >>= 1)
                pr += __shfl_xor_sync(0xffffffff, pr, off);
            l[c] = pr + bsh[c];
        }
        float mx = l[0];
        #pragma unroll
        for (int c = 1; c < 8; c++) mx = fmaxf(mx, l[c]);
        float se = 0.f;
        #pragma unroll
        for (int c = 0; c < 8; c++) se += expf(l[c] - mx);
        float lse = mx + logf(se);
        float myl = 0.f;
        #pragma unroll
        for (int c = 0; c < 8; c++) myl = (f2 == c) ? l[c] : myl;
        if (f2 < 8) out[(size_t)node * 8 + f2] = myl - lse;
    } else {
        float2 st; st.x = a0; st.y = a1;
        *reinterpret_cast<float2*>(&O[(size_t)node * FW + f]) = st;
    }
}

// ---------------- host ----------------
extern "C" void kernel_launch(void* const* d_in, const int* in_sizes, int n_in,
                              void* d_out, int out_size)
{
    int n = in_sizes[0] / 128;     // x: [N,128]
    int E = in_sizes[1] / 2;       // edge_index: [2,E]

    bool dictOrder = in_sizes[6] > 512;

    const float* x    = (const float*)d_in[0];
    const void*  eidx = d_in[1];
    const float* w_in = (const float*)d_in[2];
    const float* b_in = (const float*)d_in[3];
    const float* w1   = (const float*)d_in[4];
    const float* b1   = (const float*)d_in[5];
    const float *w2, *b2, *w3, *b3, *w_out, *b_out;
    const float *G1, *BE1, *M1, *V1, *G2, *BE2, *M2, *V2, *G3, *BE3, *M3, *V3;
    if (dictOrder) {
        w2 = (const float*)d_in[6];  b2 = (const float*)d_in[7];
        w3 = (const float*)d_in[8];  b3 = (const float*)d_in[9];
        w_out = (const float*)d_in[10]; b_out = (const float*)d_in[11];
        G1 = (const float*)d_in[12]; BE1 = (const float*)d_in[13];
        M1 = (const float*)d_in[14]; V1  = (const float*)d_in[15];
        G2 = (const float*)d_in[16]; BE2 = (const float*)d_in[17];
        M2 = (const float*)d_in[18]; V2  = (const float*)d_in[19];
        G3 = (const float*)d_in[20]; BE3 = (const float*)d_in[21];
        M3 = (const float*)d_in[22]; V3  = (const float*)d_in[23];
    } else {
        G1 = (const float*)d_in[6];  BE1 = (const float*)d_in[7];
        M1 = (const float*)d_in[8];  V1  = (const float*)d_in[9];
        w2 = (const float*)d_in[10]; b2  = (const float*)d_in[11];
        G2 = (const float*)d_in[12]; BE2 = (const float*)d_in[13];
        M2 = (const float*)d_in[14]; V2  = (const float*)d_in[15];
        w3 = (const float*)d_in[16]; b3  = (const float*)d_in[17];
        G3 = (const float*)d_in[18]; BE3 = (const float*)d_in[19];
        M3 = (const float*)d_in[20]; V3  = (const float*)d_in[21];
        w_out = (const float*)d_in[22]; b_out = (const float*)d_in[23];
    }

    float *h0p, *tp, *hp;
    cudaGetSymbolAddress((void**)&h0p, g_h0);
    cudaGetSymbolAddress((void**)&tp,  g_t);
    cudaGetSymbolAddress((void**)&hp,  g_h);

    const int TB = 256;
    int gbE = (E + TB - 1) / TB;
    int gbN = (n + TB - 1) / TB;
    int gbG = (n + 63) / 64;

    // ---- graph preprocessing ----
    k_init<<<gbN, TB>>>(eidx, n);
    k_count<<<gbE, TB>>>(eidx, E);
    k_scan_node<<<1, 1024>>>(n);
    k_fill_edges<<<gbE, TB>>>(eidx, E);

    // h0 = relu(x @ w_in + b_in)                               [N,64]
    k_gemm<128, 64, 1><<<gbG, 256>>>(x, w_in, b_in,
                                     nullptr, nullptr, nullptr, nullptr, h0p, n);
    // t1 = A @ h0   (launch idx 5 -> profiled by ncu)          [N,64]
    {
        dim3 blk(32, 4);
        k_agg<64, 0><<<(n + 3) / 4, blk>>>(h0p, tp, nullptr, nullptr, nullptr,
                                           nullptr, nullptr, nullptr, nullptr,
                                           nullptr, n);
    }
    // h1 = relu(bn1(t1 @ w1 + b1))                             [N,128]
    k_gemm<64, 128, 2><<<gbG, 256>>>(tp, w1, b1, G1, BE1, M1, V1, hp, n);
    // t2 = A @ h1                                              [N,128]
    {
        dim3 blk(64, 2);
        k_agg<128, 0><<<(n + 1) / 2, blk>>>(hp, tp, nullptr, nullptr, nullptr,
                                            nullptr, nullptr, nullptr, nullptr,
                                            nullptr, n);
    }
    // h2 = relu(bn2(t2 @ w2 + b2))                             [N,128]
    k_gemm<128, 128, 2><<<gbG, 256>>>(tp, w2, b2, G2, BE2, M2, V2, hp, n);
    // t3 = h2 @ w3                                             [N,64]
    k_gemm<128, 64, 0><<<gbG, 256>>>(hp, w3, nullptr,
                                     nullptr, nullptr, nullptr, nullptr, tp, n);
    // fused: h3 = relu(bn3(A @ t3 + b3)); out = log_softmax(h3 @ w_out + b_out)
    {
        dim3 blk(32, 4);
        k_agg<64, 2><<<(n + 3) / 4, blk>>>(tp, nullptr, b3, G3, BE3, M3, V3,
                                           w_out, b_out, (float*)d_out, n);
    }
}

// round 7
// speedup vs baseline: 1.0138x; 1.0138x over previous
#include <cuda_runtime.h>
#include <math.h>

#define NMAX 100000
#define EMAX 1600000
#define BN_EPS 1e-5f

// ---------------- device scratch (zero-initialized at module load) ----------
__device__ int   g_src[EMAX];
__device__ int   g_dstA[EMAX];
__device__ int   g_deg[NMAX];          // invariant: all-zero at entry of each call
__device__ float g_dinv[NMAX];
__device__ int   g_rowptr[NMAX + 1];
__device__ int   g_cursor[NMAX];
__device__ unsigned long long g_edge[EMAX + NMAX];   // low32 = col, high32 = weight
__device__ float g_h0[(size_t)NMAX * 64];
__device__ float g_t [(size_t)NMAX * 128];
__device__ float g_h [(size_t)NMAX * 128];

// ---------------- packed f32x2 helpers ----------------
__device__ __forceinline__ unsigned long long pk2(float x, float y) {
    unsigned long long r;
    asm("mov.b64 %0, {%1, %2};" : "=l"(r) : "f"(x), "f"(y));
    return r;
}
__device__ __forceinline__ void upk2(float& x, float& y, unsigned long long v) {
    asm("mov.b64 {%0, %1}, %2;" : "=f"(x), "=f"(y) : "l"(v));
}
#define FMA2(acc, a, b) asm("fma.rn.f32x2 %0, %1, %2, %0;" : "+l"(acc) : "l"(a), "l"(b))

// ---------------- preprocessing ----------------

// convert to int32 src/dst (staged) + count in-degree; int64-vs-int32 detected
// per block from the first 64 words (all blocks see identical data -> same
// answer; deterministic).
__global__ __launch_bounds__(256) void k_convert_count(const void* eidx, int E) {
    __shared__ int sIs64;
    {
        int lane = threadIdx.x & 31;
        if (threadIdx.x < 32) {
            const unsigned int* p = (const unsigned int*)eidx;
            unsigned int ok = (p[2 * lane + 1] == 0u);
            unsigned int bal = __ballot_sync(0xffffffff, ok);
            if (lane == 0) sIs64 = (bal == 0xffffffffu);
        }
    }
    __syncthreads();
    int i = blockIdx.x * blockDim.x + threadIdx.x;
    if (i >= E) return;
    int s, d;
    if (sIs64) {
        const long long* p = (const long long*)eidx;
        s = (int)p[i];
        d = (int)p[(size_t)E + i];
    } else {
        const int* p = (const int*)eidx;
        s = p[i];
        d = p[E + i];
    }
    g_src[i] = s;
    g_dstA[i] = d;
    atomicAdd(&g_deg[d], 1);
}

// single-block: exclusive scan of (deg[i]+1) -> rowptr, plus per-node work:
// dinv, cursor init, self-loop placed in last CSR slot of each row.
__global__ void k_scan_node(int n) {
    __shared__ int s[1024];
    int t = threadIdx.x;
    int chunk = (n + 1023) / 1024;
    int lo = t * chunk;
    int hi = lo + chunk; if (hi > n) hi = n;
    int sum = 0;
    if (lo < n) for (int i = lo; i < hi; i++) sum += g_deg[i] + 1;
    s[t] = sum;
    __syncthreads();
    for (int d = 1; d < 1024; d <<= 1) {
        int v = 0;
        if (t >= d) v = s[t - d];
        __syncthreads();
        s[t] += v;
        __syncthreads();
    }
    int off = (t == 0) ? 0 : s[t - 1];
    if (lo < n) {
        int run = off;
        for (int i = lo; i < hi; i++) {
            int deg = g_deg[i];
            g_rowptr[i] = run;
            g_cursor[i] = run;
            float di = rsqrtf((float)(deg + 1));
            g_dinv[i] = di;
            g_edge[run + deg] = ((unsigned long long)__float_as_uint(di * di) << 32) |
                                (unsigned long long)(unsigned int)i;
            run += deg + 1;
        }
    }
    if (t == 1023) g_rowptr[n] = s[1023];
}

// ---------------- GEMM body (round-2 form, refactored for reuse) ------------
// EPI: 0 = none, 1 = bias+relu, 2 = bias+bn+relu
template <int FIN, int FOUT, int EPI>
__device__ __forceinline__ void gemm_body(
    const float* __restrict__ A, const float* __restrict__ W,
    const float* __restrict__ bias,
    const float* __restrict__ gm, const float* __restrict__ bt,
    const float* __restrict__ mn, const float* __restrict__ vr,
    float* __restrict__ C, int n, int bid)
{
    constexpr int BM = 64, KC = 32;
    constexpr int NTC = FOUT / 4;        // thread cols (4 outputs each)
    constexpr int NTR = 256 / NTC;       // thread rows
    constexpr int TM  = BM / NTR;        // rows per thread

    __shared__ unsigned long long As2[BM][KC + 1];   // {a,a} duplicated pairs
    __shared__ float Ws[KC][FOUT];

    int tid = threadIdx.x;
    int rowBase = bid * BM;
    int colT = tid % NTC;
    int rowT = tid / NTC;
    int col0 = colT * 4;

    unsigned long long acc2[TM][2];
    #pragma unroll
    for (int r = 0; r < TM; r++) { acc2[r][0] = 0ull; acc2[r][1] = 0ull; }

    for (int k0 = 0; k0 < FIN; k0 += KC) {
        #pragma unroll
        for (int j = 0; j < 2; j++) {
            int idx = tid + 256 * j;
            int r = idx >> 3, c4 = idx & 7;
            int grow = rowBase + r;
            float4 v = make_float4(0.f, 0.f, 0.f, 0.f);
            if (grow < n)
                v = *reinterpret_cast<const float4*>(&A[(size_t)grow * FIN + k0 + c4 * 4]);
            As2[r][c4 * 4 + 0] = pk2(v.x, v.x);
            As2[r][c4 * 4 + 1] = pk2(v.y, v.y);
            As2[r][c4 * 4 + 2] = pk2(v.z, v.z);
            As2[r][c4 * 4 + 3] = pk2(v.w, v.w);
        }
        constexpr int WV = KC * FOUT / 4;
        #pragma unroll
        for (int j = 0; j < WV / 256; j++) {
            int idx = tid + 256 * j;
            int r = idx / (FOUT / 4), c4 = idx % (FOUT / 4);
            float4 v = *reinterpret_cast<const float4*>(&W[(size_t)(k0 + r) * FOUT + c4 * 4]);
            *reinterpret_cast<float4*>(&Ws[r][c4 * 4]) = v;
        }
        __syncthreads();
        #pragma unroll
        for (int kk = 0; kk < KC; kk++) {
            ulonglong2 wv = *reinterpret_cast<const ulonglong2*>(&Ws[kk][col0]);
            #pragma unroll
            for (int r = 0; r < TM; r++) {
                unsigned long long a2 = As2[rowT * TM + r][kk];
                FMA2(acc2[r][0], a2, wv.x);
                FMA2(acc2[r][1], a2, wv.y);
            }
        }
        __syncthreads();
    }

    float s[4] = {1.f, 1.f, 1.f, 1.f};
    float t[4] = {0.f, 0.f, 0.f, 0.f};
    if constexpr (EPI == 1) {
        #pragma unroll
        for (int c = 0; c < 4; c++) t[c] = bias[col0 + c];
    } else if constexpr (EPI == 2) {
        #pragma unroll
        for (int c = 0; c < 4; c++) {
            int cc = col0 + c;
            float sc = gm[cc] * rsqrtf(vr[cc] + BN_EPS);
            s[c] = sc;
            t[c] = (bias[cc] - mn[cc]) * sc + bt[cc];
        }
    }

    #pragma unroll
    for (int r = 0; r < TM; r++) {
        int grow = rowBase + rowT * TM + r;
        if (grow >= n) continue;
        float v0, v1, v2, v3;
        upk2(v0, v1, acc2[r][0]);
        upk2(v2, v3, acc2[r][1]);
        v0 = v0 * s[0] + t[0];
        v1 = v1 * s[1] + t[1];
        v2 = v2 * s[2] + t[2];
        v3 = v3 * s[3] + t[3];
        if constexpr (EPI != 0) {
            v0 = fmaxf(v0, 0.f); v1 = fmaxf(v1, 0.f);
            v2 = fmaxf(v2, 0.f); v3 = fmaxf(v3, 0.f);
        }
        float4 st; st.x = v0; st.y = v1; st.z = v2; st.w = v3;
        *reinterpret_cast<float4*>(&C[(size_t)grow * FOUT + col0]) = st;
    }
}

template <int FIN, int FOUT, int EPI>
__global__ __launch_bounds__(256) void k_gemm(
    const float* __restrict__ A, const float* __restrict__ W,
    const float* __restrict__ bias,
    const float* __restrict__ gm, const float* __restrict__ bt,
    const float* __restrict__ mn, const float* __restrict__ vr,
    float* __restrict__ C, int n)
{
    gemm_body<FIN, FOUT, EPI>(A, W, bias, gm, bt, mn, vr, C, n, blockIdx.x);
}

// fused: blocks [0, gbE) scatter edges into CSR; blocks [gbE, ...) run gemm0.
__global__ __launch_bounds__(256) void k_fill_gemm0(
    int E, int gbE,
    const float* __restrict__ x, const float* __restrict__ w_in,
    const float* __restrict__ b_in, float* __restrict__ h0, int n)
{
    if ((int)blockIdx.x < gbE) {
        int e = blockIdx.x * blockDim.x + threadIdx.x;
        if (e >= E) return;
        int s = g_src[e], d = g_dstA[e];
        int pos = atomicAdd(&g_cursor[d], 1);
        float w = g_dinv[s] * g_dinv[d];
        g_edge[pos] = ((unsigned long long)__float_as_uint(w) << 32) |
                      (unsigned long long)(unsigned int)s;
    } else {
        gemm_body<128, 64, 1>(x, w_in, b_in, nullptr, nullptr, nullptr, nullptr,
                              h0, n, (int)blockIdx.x - gbE);
    }
}

// ---------------- aggregation: O[i] = sum_e w[e]*H[col[e]] (round-2 form) ----
// 2 feats per thread (FFMA2), FW/2 threads per node, 128-thread blocks.
// EPI: 0 = none, 1 = bias+bn+relu
template <int FW, int EPI>
__global__ __launch_bounds__(128) void k_agg(
    const float* __restrict__ H, float* __restrict__ O,
    const float* __restrict__ b,
    const float* __restrict__ gm, const float* __restrict__ bt,
    const float* __restrict__ mn, const float* __restrict__ vr,
    int n)
{
    constexpr int TPN = FW / 2;            // threads per node
    constexpr int NPB = 128 / TPN;         // nodes per block
    int node = blockIdx.x * NPB + threadIdx.y;
    if (node >= n) return;
    int f2 = threadIdx.x;                  // feature pair index

    int s = g_rowptr[node], e = g_rowptr[node + 1];
    unsigned long long accA = 0ull, accB = 0ull;
    int p = s;
    for (; p + 2 <= e; p += 2) {
        unsigned long long e0 = g_edge[p];
        unsigned long long e1 = g_edge[p + 1];
        int c0 = (int)(unsigned int)e0;
        int c1 = (int)(unsigned int)e1;
        unsigned long long w0 = pk2(__uint_as_float((unsigned int)(e0 >> 32)),
                                    __uint_as_float((unsigned int)(e0 >> 32)));
        unsigned long long w1 = pk2(__uint_as_float((unsigned int)(e1 >> 32)),
                                    __uint_as_float((unsigned int)(e1 >> 32)));
        unsigned long long h0 = *reinterpret_cast<const unsigned long long*>(
            &H[(size_t)c0 * FW + 2 * f2]);
        unsigned long long h1 = *reinterpret_cast<const unsigned long long*>(
            &H[(size_t)c1 * FW + 2 * f2]);
        FMA2(accA, w0, h0);
        FMA2(accB, w1, h1);
    }
    if (p < e) {
        unsigned long long e0 = g_edge[p];
        int c0 = (int)(unsigned int)e0;
        float w = __uint_as_float((unsigned int)(e0 >> 32));
        unsigned long long w0 = pk2(w, w);
        unsigned long long h0 = *reinterpret_cast<const unsigned long long*>(
            &H[(size_t)c0 * FW + 2 * f2]);
        FMA2(accA, w0, h0);
    }

    float a0, a1, b0, b1;
    upk2(a0, a1, accA);
    upk2(b0, b1, accB);
    a0 += b0; a1 += b1;

    int f = 2 * f2;
    if constexpr (EPI == 1) {
        float sc0 = gm[f] * rsqrtf(vr[f] + BN_EPS);
        float sc1 = gm[f + 1] * rsqrtf(vr[f + 1] + BN_EPS);
        float v0 = (a0 + b[f] - mn[f]) * sc0 + bt[f];
        float v1 = (a1 + b[f + 1] - mn[f + 1]) * sc1 + bt[f + 1];
        float2 st; st.x = fmaxf(v0, 0.f); st.y = fmaxf(v1, 0.f);
        *reinterpret_cast<float2*>(&O[(size_t)node * FW + f]) = st;
    } else {
        float2 st; st.x = a0; st.y = a1;
        *reinterpret_cast<float2*>(&O[(size_t)node * FW + f]) = st;
    }
}

// ---------------- final: logits = H @ w_out + b_out; log_softmax -------------
// Also re-zeroes g_deg for the next kernel_launch call (8 entries per block).
__global__ __launch_bounds__(256) void k_out(
    const float* __restrict__ H, const float* __restrict__ Wo,
    const float* __restrict__ bo, float* __restrict__ out, int n)
{
    __shared__ float wsT[8 * 64];   // [c][f]
    __shared__ float bsh[8];
    int tid = threadIdx.x;

    // cleanup for next call: restore g_deg == 0 invariant
    {
        int z = blockIdx.x * 8 + tid;
        if (tid < 8 && z < n) g_deg[z] = 0;
    }

    for (int idx = tid; idx < 512; idx += 256) {
        int f = idx >> 3, c = idx & 7;
        wsT[c * 64 + f] = Wo[idx];
    }
    if (tid < 8) bsh[tid] = bo[tid];
    __syncthreads();

    int warp = tid >> 5, lane = tid & 31;
    int node = blockIdx.x * 8 + warp;
    if (node >= n) return;

    float ha = H[(size_t)node * 64 + lane];
    float hb = H[(size_t)node * 64 + 32 + lane];
    float l[8];
    #pragma unroll
    for (int c = 0; c < 8; c++) {
        float p = ha * wsT[c * 64 + lane] + hb * wsT[c * 64 + 32 + lane];
        #pragma unroll
        for (int off = 16; off; off >>= 1) p += __shfl_xor_sync(0xffffffff, p, off);
        l[c] = p + bsh[c];
    }
    float mx = l[0];
    #pragma unroll
    for (int c = 1; c < 8; c++) mx = fmaxf(mx, l[c]);
    float se = 0.f;
    #pragma unroll
    for (int c = 0; c < 8; c++) se += expf(l[c] - mx);
    float lse = mx + logf(se);
    if (lane < 8) out[(size_t)node * 8 + lane] = l[lane] - lse;
}

// ---------------- host ----------------
extern "C" void kernel_launch(void* const* d_in, const int* in_sizes, int n_in,
                              void* d_out, int out_size)
{
    int n = in_sizes[0] / 128;     // x: [N,128]
    int E = in_sizes[1] / 2;       // edge_index: [2,E]

    bool dictOrder = in_sizes[6] > 512;

    const float* x    = (const float*)d_in[0];
    const void*  eidx = d_in[1];
    const float* w_in = (const float*)d_in[2];
    const float* b_in = (const float*)d_in[3];
    const float* w1   = (const float*)d_in[4];
    const float* b1   = (const float*)d_in[5];
    const float *w2, *b2, *w3, *b3, *w_out, *b_out;
    const float *G1, *BE1, *M1, *V1, *G2, *BE2, *M2, *V2, *G3, *BE3, *M3, *V3;
    if (dictOrder) {
        w2 = (const float*)d_in[6];  b2 = (const float*)d_in[7];
        w3 = (const float*)d_in[8];  b3 = (const float*)d_in[9];
        w_out = (const float*)d_in[10]; b_out = (const float*)d_in[11];
        G1 = (const float*)d_in[12]; BE1 = (const float*)d_in[13];
        M1 = (const float*)d_in[14]; V1  = (const float*)d_in[15];
        G2 = (const float*)d_in[16]; BE2 = (const float*)d_in[17];
        M2 = (const float*)d_in[18]; V2  = (const float*)d_in[19];
        G3 = (const float*)d_in[20]; BE3 = (const float*)d_in[21];
        M3 = (const float*)d_in[22]; V3  = (const float*)d_in[23];
    } else {
        G1 = (const float*)d_in[6];  BE1 = (const float*)d_in[7];
        M1 = (const float*)d_in[8];  V1  = (const float*)d_in[9];
        w2 = (const float*)d_in[10]; b2  = (const float*)d_in[11];
        G2 = (const float*)d_in[12]; BE2 = (const float*)d_in[13];
        M2 = (const float*)d_in[14]; V2  = (const float*)d_in[15];
        w3 = (const float*)d_in[16]; b3  = (const float*)d_in[17];
        G3 = (const float*)d_in[18]; BE3 = (const float*)d_in[19];
        M3 = (const float*)d_in[20]; V3  = (const float*)d_in[21];
        w_out = (const float*)d_in[22]; b_out = (const float*)d_in[23];
    }

    float *h0p, *tp, *hp;
    cudaGetSymbolAddress((void**)&h0p, g_h0);
    cudaGetSymbolAddress((void**)&tp,  g_t);
    cudaGetSymbolAddress((void**)&hp,  g_h);

    const int TB = 256;
    int gbE = (E + TB - 1) / TB;
    int gbG = (n + 63) / 64;

    // idx 0: convert + stage + degree count (g_deg zeroed by prior call / load)
    k_convert_count<<<gbE, TB>>>(eidx, E);
    // idx 1: scan + dinv + cursor + self-loops
    k_scan_node<<<1, 1024>>>(n);
    // idx 2: fused edge scatter + gemm0: h0 = relu(x @ w_in + b_in)   [N,64]
    k_fill_gemm0<<<gbE + gbG, TB>>>(E, gbE, x, w_in, b_in, h0p, n);
    // idx 3 (PROFILED): t1 = A @ h0                                   [N,64]
    {
        dim3 blk(32, 4);
        k_agg<64, 0><<<(n + 3) / 4, blk>>>(h0p, tp, nullptr, nullptr, nullptr,
                                           nullptr, nullptr, n);
    }
    // h1 = relu(bn1(t1 @ w1 + b1))                                    [N,128]
    k_gemm<64, 128, 2><<<gbG, 256>>>(tp, w1, b1, G1, BE1, M1, V1, hp, n);
    // t2 = A @ h1                                                     [N,128]
    {
        dim3 blk(64, 2);
        k_agg<128, 0><<<(n + 1) / 2, blk>>>(hp, tp, nullptr, nullptr, nullptr,
                                            nullptr, nullptr, n);
    }
    // h2 = relu(bn2(t2 @ w2 + b2))                                    [N,128]
    k_gemm<128, 128, 2><<<gbG, 256>>>(tp, w2, b2, G2, BE2, M2, V2, hp, n);
    // t3 = h2 @ w3                                                    [N,64]
    k_gemm<128, 64, 0><<<gbG, 256>>>(hp, w3, nullptr,
                                     nullptr, nullptr, nullptr, nullptr, tp, n);
    // h3 = relu(bn3(A @ t3 + b3))                                     [N,64]
    {
        dim3 blk(32, 4);
        k_agg<64, 1><<<(n + 3) / 4, blk>>>(tp, hp, b3, G3, BE3, M3, V3, n);
    }
    // out = log_softmax(h3 @ w_out + b_out)  (+ g_deg cleanup)        [N,8]
    k_out<<<(n + 7) / 8, 256>>>(hp, w_out, b_out, (float*)d_out, n);
}

// round 8
// speedup vs baseline: 1.0784x; 1.0637x over previous
#include <cuda_runtime.h>
#include <math.h>

#define NMAX 100000
#define EMAX 1600000
#define BN_EPS 1e-5f

// ---------------- device scratch (zero-initialized at module load) ----------
__device__ int   g_src[EMAX];
__device__ int   g_dstA[EMAX];
__device__ int   g_deg[NMAX];          // invariant: all-zero at entry of each call
__device__ float g_dinv[NMAX];
__device__ int   g_rowptr[NMAX + 1];
__device__ int   g_cursor[NMAX];
__device__ unsigned long long g_edge[EMAX + NMAX];   // low32 = col, high32 = weight
__device__ float g_h0[(size_t)NMAX * 64];
__device__ float g_t [(size_t)NMAX * 128];
__device__ float g_h [(size_t)NMAX * 128];

// ---------------- packed f32x2 helpers ----------------
__device__ __forceinline__ unsigned long long pk2(float x, float y) {
    unsigned long long r;
    asm("mov.b64 %0, {%1, %2};" : "=l"(r) : "f"(x), "f"(y));
    return r;
}
__device__ __forceinline__ void upk2(float& x, float& y, unsigned long long v) {
    asm("mov.b64 {%0, %1}, %2;" : "=f"(x), "=f"(y) : "l"(v));
}
#define FMA2(acc, a, b) asm("fma.rn.f32x2 %0, %1, %2, %0;" : "+l"(acc) : "l"(a), "l"(b))

// ---------------- preprocessing ----------------

// convert to int32 src/dst (staged) + count in-degree; int64-vs-int32 detected
// per block from the first 64 words (identical data -> identical answer).
__global__ __launch_bounds__(256) void k_convert_count(const void* eidx, int E) {
    __shared__ int sIs64;
    {
        int lane = threadIdx.x & 31;
        if (threadIdx.x < 32) {
            const unsigned int* p = (const unsigned int*)eidx;
            unsigned int ok = (p[2 * lane + 1] == 0u);
            unsigned int bal = __ballot_sync(0xffffffff, ok);
            if (lane == 0) sIs64 = (bal == 0xffffffffu);
        }
    }
    __syncthreads();
    int i = blockIdx.x * blockDim.x + threadIdx.x;
    if (i >= E) return;
    int s, d;
    if (sIs64) {
        const long long* p = (const long long*)eidx;
        s = (int)p[i];
        d = (int)p[(size_t)E + i];
    } else {
        const int* p = (const int*)eidx;
        s = p[i];
        d = p[E + i];
    }
    g_src[i] = s;
    g_dstA[i] = d;
    atomicAdd(&g_deg[d], 1);
}

// single-block: exclusive scan of (deg[i]+1) -> rowptr, plus per-node work:
// dinv, cursor init, self-loop placed in last CSR slot of each row.
__global__ void k_scan_node(int n) {
    __shared__ int s[1024];
    int t = threadIdx.x;
    int chunk = (n + 1023) / 1024;
    int lo = t * chunk;
    int hi = lo + chunk; if (hi > n) hi = n;
    int sum = 0;
    if (lo < n) for (int i = lo; i < hi; i++) sum += g_deg[i] + 1;
    s[t] = sum;
    __syncthreads();
    for (int d = 1; d < 1024; d <<= 1) {
        int v = 0;
        if (t >= d) v = s[t - d];
        __syncthreads();
        s[t] += v;
        __syncthreads();
    }
    int off = (t == 0) ? 0 : s[t - 1];
    if (lo < n) {
        int run = off;
        for (int i = lo; i < hi; i++) {
            int deg = g_deg[i];
            g_rowptr[i] = run;
            g_cursor[i] = run;
            float di = rsqrtf((float)(deg + 1));
            g_dinv[i] = di;
            g_edge[run + deg] = ((unsigned long long)__float_as_uint(di * di) << 32) |
                                (unsigned long long)(unsigned int)i;
            run += deg + 1;
        }
    }
    if (t == 1023) g_rowptr[n] = s[1023];
}

// ---------------- GEMM body (round-2 form) ------------
// EPI: 0 = none, 1 = bias+relu, 2 = bias+bn+relu
template <int FIN, int FOUT, int EPI>
__device__ __forceinline__ void gemm_body(
    const float* __restrict__ A, const float* __restrict__ W,
    const float* __restrict__ bias,
    const float* __restrict__ gm, const float* __restrict__ bt,
    const float* __restrict__ mn, const float* __restrict__ vr,
    float* __restrict__ C, int n, int bid)
{
    constexpr int BM = 64, KC = 32;
    constexpr int NTC = FOUT / 4;        // thread cols (4 outputs each)
    constexpr int NTR = 256 / NTC;       // thread rows
    constexpr int TM  = BM / NTR;        // rows per thread

    __shared__ unsigned long long As2[BM][KC + 1];   // {a,a} duplicated pairs
    __shared__ float Ws[KC][FOUT];

    int tid = threadIdx.x;
    int rowBase = bid * BM;
    int colT = tid % NTC;
    int rowT = tid / NTC;
    int col0 = colT * 4;

    unsigned long long acc2[TM][2];
    #pragma unroll
    for (int r = 0; r < TM; r++) { acc2[r][0] = 0ull; acc2[r][1] = 0ull; }

    for (int k0 = 0; k0 < FIN; k0 += KC) {
        #pragma unroll
        for (int j = 0; j < 2; j++) {
            int idx = tid + 256 * j;
            int r = idx >> 3, c4 = idx & 7;
            int grow = rowBase + r;
            float4 v = make_float4(0.f, 0.f, 0.f, 0.f);
            if (grow < n)
                v = *reinterpret_cast<const float4*>(&A[(size_t)grow * FIN + k0 + c4 * 4]);
            As2[r][c4 * 4 + 0] = pk2(v.x, v.x);
            As2[r][c4 * 4 + 1] = pk2(v.y, v.y);
            As2[r][c4 * 4 + 2] = pk2(v.z, v.z);
            As2[r][c4 * 4 + 3] = pk2(v.w, v.w);
        }
        constexpr int WV = KC * FOUT / 4;
        #pragma unroll
        for (int j = 0; j < WV / 256; j++) {
            int idx = tid + 256 * j;
            int r = idx / (FOUT / 4), c4 = idx % (FOUT / 4);
            float4 v = *reinterpret_cast<const float4*>(&W[(size_t)(k0 + r) * FOUT + c4 * 4]);
            *reinterpret_cast<float4*>(&Ws[r][c4 * 4]) = v;
        }
        __syncthreads();
        #pragma unroll
        for (int kk = 0; kk < KC; kk++) {
            ulonglong2 wv = *reinterpret_cast<const ulonglong2*>(&Ws[kk][col0]);
            #pragma unroll
            for (int r = 0; r < TM; r++) {
                unsigned long long a2 = As2[rowT * TM + r][kk];
                FMA2(acc2[r][0], a2, wv.x);
                FMA2(acc2[r][1], a2, wv.y);
            }
        }
        __syncthreads();
    }

    float s[4] = {1.f, 1.f, 1.f, 1.f};
    float t[4] = {0.f, 0.f, 0.f, 0.f};
    if constexpr (EPI == 1) {
        #pragma unroll
        for (int c = 0; c < 4; c++) t[c] = bias[col0 + c];
    } else if constexpr (EPI == 2) {
        #pragma unroll
        for (int c = 0; c < 4; c++) {
            int cc = col0 + c;
            float sc = gm[cc] * rsqrtf(vr[cc] + BN_EPS);
            s[c] = sc;
            t[c] = (bias[cc] - mn[cc]) * sc + bt[cc];
        }
    }

    #pragma unroll
    for (int r = 0; r < TM; r++) {
        int grow = rowBase + rowT * TM + r;
        if (grow >= n) continue;
        float v0, v1, v2, v3;
        upk2(v0, v1, acc2[r][0]);
        upk2(v2, v3, acc2[r][1]);
        v0 = v0 * s[0] + t[0];
        v1 = v1 * s[1] + t[1];
        v2 = v2 * s[2] + t[2];
        v3 = v3 * s[3] + t[3];
        if constexpr (EPI != 0) {
            v0 = fmaxf(v0, 0.f); v1 = fmaxf(v1, 0.f);
            v2 = fmaxf(v2, 0.f); v3 = fmaxf(v3, 0.f);
        }
        float4 st; st.x = v0; st.y = v1; st.z = v2; st.w = v3;
        *reinterpret_cast<float4*>(&C[(size_t)grow * FOUT + col0]) = st;
    }
}

template <int FIN, int FOUT, int EPI>
__global__ __launch_bounds__(256) void k_gemm(
    const float* __restrict__ A, const float* __restrict__ W,
    const float* __restrict__ bias,
    const float* __restrict__ gm, const float* __restrict__ bt,
    const float* __restrict__ mn, const float* __restrict__ vr,
    float* __restrict__ C, int n)
{
    gemm_body<FIN, FOUT, EPI>(A, W, bias, gm, bt, mn, vr, C, n, blockIdx.x);
}

// fused: blocks [0, gbE) scatter edges into CSR; blocks [gbE, ...) run gemm0.
__global__ __launch_bounds__(256) void k_fill_gemm0(
    int E, int gbE,
    const float* __restrict__ x, const float* __restrict__ w_in,
    const float* __restrict__ b_in, float* __restrict__ h0, int n)
{
    if ((int)blockIdx.x < gbE) {
        int e = blockIdx.x * blockDim.x + threadIdx.x;
        if (e >= E) return;
        int s = g_src[e], d = g_dstA[e];
        int pos = atomicAdd(&g_cursor[d], 1);
        float w = g_dinv[s] * g_dinv[d];
        g_edge[pos] = ((unsigned long long)__float_as_uint(w) << 32) |
                      (unsigned long long)(unsigned int)s;
    } else {
        gemm_body<128, 64, 1>(x, w_in, b_in, nullptr, nullptr, nullptr, nullptr,
                              h0, n, (int)blockIdx.x - gbE);
    }
}

// ---------------- aggregation: O[i] = sum_e w[e]*H[col[e]] -------------------
// float4 gathers: FW/4 threads per node, 4 feats/thread, FFMA2 math.
// EPI 0: store raw sums. EPI 2 (FW=64 only): bn+relu, then fused
//        (h @ w_out + b_out) -> log_softmax via 16-lane xor reduction;
//        also re-zeroes g_deg (this is the last kernel of the call).
template <int FW, int EPI>
__global__ __launch_bounds__(128) void k_agg(
    const float* __restrict__ H, float* __restrict__ O,
    const float* __restrict__ b,
    const float* __restrict__ gm, const float* __restrict__ bt,
    const float* __restrict__ mn, const float* __restrict__ vr,
    const float* __restrict__ Wo, const float* __restrict__ bo,
    float* __restrict__ out, int n)
{
    constexpr int TPN = FW / 4;            // threads per node (16 or 32)
    constexpr int NPB = 128 / TPN;         // nodes per block  (8 or 4)

    __shared__ float wsT[8 * 64];          // [c][f]  (EPI==2 only)
    __shared__ float bsh[8];
    int tidF = threadIdx.y * TPN + threadIdx.x;
    if constexpr (EPI == 2) {
        for (int idx = tidF; idx < 512; idx += 128) {
            int f = idx >> 3, c = idx & 7;
            wsT[c * 64 + f] = Wo[idx];
        }
        if (tidF < 8) bsh[tidF] = bo[tidF];
        // cleanup for next call: restore g_deg == 0 invariant
        if (tidF < NPB) {
            int z = blockIdx.x * NPB + tidF;
            if (z < n) g_deg[z] = 0;
        }
        __syncthreads();
    }

    int node = blockIdx.x * NPB + threadIdx.y;
    if (node >= n) return;
    int f4 = threadIdx.x;                  // feature-quad index

    const float* Hq = H + 4 * f4;
    int s = g_rowptr[node], e = g_rowptr[node + 1];
    ulonglong2 accA, accB;
    accA.x = accA.y = accB.x = accB.y = 0ull;

    int p = s;
    for (; p + 2 <= e; p += 2) {
        unsigned long long e0 = g_edge[p];
        unsigned long long e1 = g_edge[p + 1];
        ulonglong2 h0 = *reinterpret_cast<const ulonglong2*>(
            &Hq[(size_t)(unsigned int)e0 * FW]);
        ulonglong2 h1 = *reinterpret_cast<const ulonglong2*>(
            &Hq[(size_t)(unsigned int)e1 * FW]);
        float w0 = __uint_as_float((unsigned int)(e0 >> 32));
        float w1 = __uint_as_float((unsigned int)(e1 >> 32));
        unsigned long long wd0 = pk2(w0, w0);
        unsigned long long wd1 = pk2(w1, w1);
        FMA2(accA.x, wd0, h0.x);
        FMA2(accA.y, wd0, h0.y);
        FMA2(accB.x, wd1, h1.x);
        FMA2(accB.y, wd1, h1.y);
    }
    if (p < e) {
        unsigned long long e0 = g_edge[p];
        ulonglong2 h0 = *reinterpret_cast<const ulonglong2*>(
            &Hq[(size_t)(unsigned int)e0 * FW]);
        float w0 = __uint_as_float((unsigned int)(e0 >> 32));
        unsigned long long wd0 = pk2(w0, w0);
        FMA2(accA.x, wd0, h0.x);
        FMA2(accA.y, wd0, h0.y);
    }

    float a0, a1, a2, a3, t0, t1;
    upk2(a0, a1, accA.x);
    upk2(a2, a3, accA.y);
    upk2(t0, t1, accB.x); a0 += t0; a1 += t1;
    upk2(t0, t1, accB.y); a2 += t0; a3 += t1;

    int f = 4 * f4;
    if constexpr (EPI == 2) {
        // bn + relu on 4 feats
        float v[4]; float av[4] = {a0, a1, a2, a3};
        #pragma unroll
        for (int c = 0; c < 4; c++) {
            int cc = f + c;
            float sc = gm[cc] * rsqrtf(vr[cc] + BN_EPS);
            v[c] = fmaxf((av[c] + b[cc] - mn[cc]) * sc + bt[cc], 0.f);
        }
        // fused 64x8 GEMM: reduce over the 16 lanes of this node subgroup
        // (xor offsets 8,4,2,1 stay within the 16-lane group)
        float l[8];
        #pragma unroll
        for (int c = 0; c < 8; c++) {
            float pr = v[0] * wsT[c * 64 + f]     + v[1] * wsT[c * 64 + f + 1]
                     + v[2] * wsT[c * 64 + f + 2] + v[3] * wsT[c * 64 + f + 3];
            #pragma unroll
            for (int off = 8; off; off >>= 1)
                pr += __shfl_xor_sync(0xffffffff, pr, off);
            l[c] = pr + bsh[c];
        }
        float mx = l[0];
        #pragma unroll
        for (int c = 1; c < 8; c++) mx = fmaxf(mx, l[c]);
        float se = 0.f;
        #pragma unroll
        for (int c = 0; c < 8; c++) se += expf(l[c] - mx);
        float lse = mx + logf(se);
        float myl = l[0];
        #pragma unroll
        for (int c = 1; c < 8; c++) myl = (f4 == c) ? l[c] : myl;
        if (f4 < 8) out[(size_t)node * 8 + f4] = myl - lse;
    } else {
        float4 st; st.x = a0; st.y = a1; st.z = a2; st.w = a3;
        *reinterpret_cast<float4*>(&O[(size_t)node * FW + f]) = st;
    }
}

// ---------------- host ----------------
extern "C" void kernel_launch(void* const* d_in, const int* in_sizes, int n_in,
                              void* d_out, int out_size)
{
    int n = in_sizes[0] / 128;     // x: [N,128]
    int E = in_sizes[1] / 2;       // edge_index: [2,E]

    bool dictOrder = in_sizes[6] > 512;

    const float* x    = (const float*)d_in[0];
    const void*  eidx = d_in[1];
    const float* w_in = (const float*)d_in[2];
    const float* b_in = (const float*)d_in[3];
    const float* w1   = (const float*)d_in[4];
    const float* b1   = (const float*)d_in[5];
    const float *w2, *b2, *w3, *b3, *w_out, *b_out;
    const float *G1, *BE1, *M1, *V1, *G2, *BE2, *M2, *V2, *G3, *BE3, *M3, *V3;
    if (dictOrder) {
        w2 = (const float*)d_in[6];  b2 = (const float*)d_in[7];
        w3 = (const float*)d_in[8];  b3 = (const float*)d_in[9];
        w_out = (const float*)d_in[10]; b_out = (const float*)d_in[11];
        G1 = (const float*)d_in[12]; BE1 = (const float*)d_in[13];
        M1 = (const float*)d_in[14]; V1  = (const float*)d_in[15];
        G2 = (const float*)d_in[16]; BE2 = (const float*)d_in[17];
        M2 = (const float*)d_in[18]; V2  = (const float*)d_in[19];
        G3 = (const float*)d_in[20]; BE3 = (const float*)d_in[21];
        M3 = (const float*)d_in[22]; V3  = (const float*)d_in[23];
    } else {
        G1 = (const float*)d_in[6];  BE1 = (const float*)d_in[7];
        M1 = (const float*)d_in[8];  V1  = (const float*)d_in[9];
        w2 = (const float*)d_in[10]; b2  = (const float*)d_in[11];
        G2 = (const float*)d_in[12]; BE2 = (const float*)d_in[13];
        M2 = (const float*)d_in[14]; V2  = (const float*)d_in[15];
        w3 = (const float*)d_in[16]; b3  = (const float*)d_in[17];
        G3 = (const float*)d_in[18]; BE3 = (const float*)d_in[19];
        M3 = (const float*)d_in[20]; V3  = (const float*)d_in[21];
        w_out = (const float*)d_in[22]; b_out = (const float*)d_in[23];
    }

    float *h0p, *tp, *hp;
    cudaGetSymbolAddress((void**)&h0p, g_h0);
    cudaGetSymbolAddress((void**)&tp,  g_t);
    cudaGetSymbolAddress((void**)&hp,  g_h);

    const int TB = 256;
    int gbE = (E + TB - 1) / TB;
    int gbG = (n + 63) / 64;

    // idx 0: convert + stage + degree count (g_deg zeroed by prior call / load)
    k_convert_count<<<gbE, TB>>>(eidx, E);
    // idx 1: scan + dinv + cursor + self-loops
    k_scan_node<<<1, 1024>>>(n);
    // idx 2: fused edge scatter + gemm0: h0 = relu(x @ w_in + b_in)   [N,64]
    k_fill_gemm0<<<gbE + gbG, TB>>>(E, gbE, x, w_in, b_in, h0p, n);
    // idx 3 (PROFILED): t1 = A @ h0                                   [N,64]
    {
        dim3 blk(16, 8);
        k_agg<64, 0><<<(n + 7) / 8, blk>>>(h0p, tp, nullptr, nullptr, nullptr,
                                           nullptr, nullptr, nullptr, nullptr,
                                           nullptr, n);
    }
    // h1 = relu(bn1(t1 @ w1 + b1))                                    [N,128]
    k_gemm<64, 128, 2><<<gbG, 256>>>(tp, w1, b1, G1, BE1, M1, V1, hp, n);
    // t2 = A @ h1                                                     [N,128]
    {
        dim3 blk(32, 4);
        k_agg<128, 0><<<(n + 3) / 4, blk>>>(hp, tp, nullptr, nullptr, nullptr,
                                            nullptr, nullptr, nullptr, nullptr,
                                            nullptr, n);
    }
    // h2 = relu(bn2(t2 @ w2 + b2))                                    [N,128]
    k_gemm<128, 128, 2><<<gbG, 256>>>(tp, w2, b2, G2, BE2, M2, V2, hp, n);
    // t3 = h2 @ w3                                                    [N,64]
    k_gemm<128, 64, 0><<<gbG, 256>>>(hp, w3, nullptr,
                                     nullptr, nullptr, nullptr, nullptr, tp, n);
    // fused final: h3 = relu(bn3(A @ t3 + b3));
    //              out = log_softmax(h3 @ w_out + b_out)  (+ g_deg cleanup)
    {
        dim3 blk(16, 8);
        k_agg<64, 2><<<(n + 7) / 8, blk>>>(tp, nullptr, b3, G3, BE3, M3, V3,
                                           w_out, b_out, (float*)d_out, n);
    }
}

// round 9
// speedup vs baseline: 1.1172x; 1.0359x over previous
#include <cuda_runtime.h>
#include <cuda_fp16.h>
#include <math.h>

#define NMAX 100000
#define EMAX 1600000
#define BN_EPS 1e-5f

// ---------------- device scratch (zero-initialized at module load) ----------
__device__ int   g_src[EMAX];
__device__ int   g_dstA[EMAX];
__device__ int   g_deg[NMAX];          // invariant: all-zero at entry of each call
__device__ float g_dinv[NMAX];
__device__ int   g_rowptr[NMAX + 1];
__device__ int   g_cursor[NMAX];
__device__ unsigned long long g_edge[EMAX + NMAX];   // low32 = col, high32 = weight
__device__ __align__(16) __half g_h0[(size_t)NMAX * 64];
__device__ __align__(16) __half g_t [(size_t)NMAX * 128];
__device__ __align__(16) __half g_h [(size_t)NMAX * 128];

// ---------------- packed f32x2 helpers ----------------
__device__ __forceinline__ unsigned long long pk2(float x, float y) {
    unsigned long long r;
    asm("mov.b64 %0, {%1, %2};" : "=l"(r) : "f"(x), "f"(y));
    return r;
}
__device__ __forceinline__ void upk2(float& x, float& y, unsigned long long v) {
    asm("mov.b64 {%0, %1}, %2;" : "=f"(x), "=f"(y) : "l"(v));
}
#define FMA2(acc, a, b) asm("fma.rn.f32x2 %0, %1, %2, %0;" : "+l"(acc) : "l"(a), "l"(b))

__device__ __forceinline__ unsigned int h2u(__half2 h) {
    return *reinterpret_cast<unsigned int*>(&h);
}

// ---------------- preprocessing ----------------

// convert to int32 src/dst (staged) + count in-degree; int64-vs-int32 detected
// per block from the first 64 words (identical data -> identical answer).
__global__ __launch_bounds__(256) void k_convert_count(const void* eidx, int E) {
    __shared__ int sIs64;
    {
        int lane = threadIdx.x & 31;
        if (threadIdx.x < 32) {
            const unsigned int* p = (const unsigned int*)eidx;
            unsigned int ok = (p[2 * lane + 1] == 0u);
            unsigned int bal = __ballot_sync(0xffffffff, ok);
            if (lane == 0) sIs64 = (bal == 0xffffffffu);
        }
    }
    __syncthreads();
    int i = blockIdx.x * blockDim.x + threadIdx.x;
    if (i >= E) return;
    int s, d;
    if (sIs64) {
        const long long* p = (const long long*)eidx;
        s = (int)p[i];
        d = (int)p[(size_t)E + i];
    } else {
        const int* p = (const int*)eidx;
        s = p[i];
        d = p[E + i];
    }
    g_src[i] = s;
    g_dstA[i] = d;
    atomicAdd(&g_deg[d], 1);
}

// single-block: exclusive scan of (deg[i]+1) -> rowptr, plus per-node work:
// dinv, cursor init, self-loop placed in last CSR slot of each row.
__global__ void k_scan_node(int n) {
    __shared__ int s[1024];
    int t = threadIdx.x;
    int chunk = (n + 1023) / 1024;
    int lo = t * chunk;
    int hi = lo + chunk; if (hi > n) hi = n;
    int sum = 0;
    if (lo < n) for (int i = lo; i < hi; i++) sum += g_deg[i] + 1;
    s[t] = sum;
    __syncthreads();
    for (int d = 1; d < 1024; d <<= 1) {
        int v = 0;
        if (t >= d) v = s[t - d];
        __syncthreads();
        s[t] += v;
        __syncthreads();
    }
    int off = (t == 0) ? 0 : s[t - 1];
    if (lo < n) {
        int run = off;
        for (int i = lo; i < hi; i++) {
            int deg = g_deg[i];
            g_rowptr[i] = run;
            g_cursor[i] = run;
            float di = rsqrtf((float)(deg + 1));
            g_dinv[i] = di;
            g_edge[run + deg] = ((unsigned long long)__float_as_uint(di * di) << 32) |
                                (unsigned long long)(unsigned int)i;
            run += deg + 1;
        }
    }
    if (t == 1023) g_rowptr[n] = s[1023];
}

// ---------------- GEMM: C[n,FOUT] = A[n,FIN] @ W[FIN,FOUT] (+ epilogue) -----
// A is fp32 (AH=false) or fp16 (AH=true); math fp32; C stored fp16.
// TM == 8 in all configs: 8 LDS.64 + 1 LDS.128 + 16 FFMA2 per kk.
// EPI: 0 = none, 1 = bias+relu, 2 = bias+bn+relu
template <int FIN, int FOUT, int BM, int EPI, bool AH>
__device__ __forceinline__ void gemm_body(
    const void* __restrict__ Av, const float* __restrict__ W,
    const float* __restrict__ bias,
    const float* __restrict__ gm, const float* __restrict__ bt,
    const float* __restrict__ mn, const float* __restrict__ vr,
    __half* __restrict__ C, int n, int bid)
{
    constexpr int KC = 32;
    constexpr int NTC = FOUT / 4;        // thread cols (4 outputs each)
    constexpr int NTR = 256 / NTC;       // thread rows
    constexpr int TM  = BM / NTR;        // rows per thread
    static_assert(TM == 8, "config");

    __shared__ unsigned long long As2[BM][KC + 1];   // {a,a} duplicated pairs
    __shared__ float Ws[KC][FOUT];

    int tid = threadIdx.x;
    int rowBase = bid * BM;
    int colT = tid % NTC;
    int rowT = tid / NTC;
    int col0 = colT * 4;
    int row0 = rowT * TM;

    unsigned long long acc2[TM][2];
    #pragma unroll
    for (int r = 0; r < TM; r++) { acc2[r][0] = 0ull; acc2[r][1] = 0ull; }

    for (int k0 = 0; k0 < FIN; k0 += KC) {
        // A tile: BM x KC values, 4-elem chunks, duplicated into {a,a} pairs
        constexpr int LD = (BM * KC / 4) / 256;
        #pragma unroll
        for (int j = 0; j < LD; j++) {
            int idx = tid + 256 * j;
            int r = idx >> 3, c4 = idx & 7;     // KC/4 == 8 chunks per row
            int grow = rowBase + r;
            float f0 = 0.f, f1 = 0.f, f2 = 0.f, f3 = 0.f;
            if (grow < n) {
                if constexpr (AH) {
                    const __half* A = (const __half*)Av;
                    uint2 lv = *reinterpret_cast<const uint2*>(
                        &A[(size_t)grow * FIN + k0 + c4 * 4]);
                    float2 a01 = __half22float2(*reinterpret_cast<__half2*>(&lv.x));
                    float2 a23 = __half22float2(*reinterpret_cast<__half2*>(&lv.y));
                    f0 = a01.x; f1 = a01.y; f2 = a23.x; f3 = a23.y;
                } else {
                    const float* A = (const float*)Av;
                    float4 v = *reinterpret_cast<const float4*>(
                        &A[(size_t)grow * FIN + k0 + c4 * 4]);
                    f0 = v.x; f1 = v.y; f2 = v.z; f3 = v.w;
                }
            }
            As2[r][c4 * 4 + 0] = pk2(f0, f0);
            As2[r][c4 * 4 + 1] = pk2(f1, f1);
            As2[r][c4 * 4 + 2] = pk2(f2, f2);
            As2[r][c4 * 4 + 3] = pk2(f3, f3);
        }
        // W tile: KC x FOUT (fp32)
        constexpr int WV = KC * FOUT / 4;
        #pragma unroll
        for (int j = 0; j < WV / 256; j++) {
            int idx = tid + 256 * j;
            int r = idx / (FOUT / 4), c4 = idx % (FOUT / 4);
            float4 v = *reinterpret_cast<const float4*>(&W[(size_t)(k0 + r) * FOUT + c4 * 4]);
            *reinterpret_cast<float4*>(&Ws[r][c4 * 4]) = v;
        }
        __syncthreads();
        #pragma unroll
        for (int kk = 0; kk < KC; kk++) {
            ulonglong2 wv = *reinterpret_cast<const ulonglong2*>(&Ws[kk][col0]);
            #pragma unroll
            for (int r = 0; r < TM; r++) {
                unsigned long long a2 = As2[row0 + r][kk];
                FMA2(acc2[r][0], a2, wv.x);
                FMA2(acc2[r][1], a2, wv.y);
            }
        }
        __syncthreads();
    }

    float s[4] = {1.f, 1.f, 1.f, 1.f};
    float t[4] = {0.f, 0.f, 0.f, 0.f};
    if constexpr (EPI == 1) {
        #pragma unroll
        for (int c = 0; c < 4; c++) t[c] = bias[col0 + c];
    } else if constexpr (EPI == 2) {
        #pragma unroll
        for (int c = 0; c < 4; c++) {
            int cc = col0 + c;
            float sc = gm[cc] * rsqrtf(vr[cc] + BN_EPS);
            s[c] = sc;
            t[c] = (bias[cc] - mn[cc]) * sc + bt[cc];
        }
    }

    #pragma unroll
    for (int r = 0; r < TM; r++) {
        int grow = rowBase + row0 + r;
        if (grow >= n) continue;
        float v0, v1, v2, v3;
        upk2(v0, v1, acc2[r][0]);
        upk2(v2, v3, acc2[r][1]);
        v0 = v0 * s[0] + t[0];
        v1 = v1 * s[1] + t[1];
        v2 = v2 * s[2] + t[2];
        v3 = v3 * s[3] + t[3];
        if constexpr (EPI != 0) {
            v0 = fmaxf(v0, 0.f); v1 = fmaxf(v1, 0.f);
            v2 = fmaxf(v2, 0.f); v3 = fmaxf(v3, 0.f);
        }
        uint2 st;
        st.x = h2u(__floats2half2_rn(v0, v1));
        st.y = h2u(__floats2half2_rn(v2, v3));
        *reinterpret_cast<uint2*>(&C[(size_t)grow * FOUT + col0]) = st;
    }
}

template <int FIN, int FOUT, int BM, int EPI, bool AH>
__global__ __launch_bounds__(256) void k_gemm(
    const void* __restrict__ A, const float* __restrict__ W,
    const float* __restrict__ bias,
    const float* __restrict__ gm, const float* __restrict__ bt,
    const float* __restrict__ mn, const float* __restrict__ vr,
    __half* __restrict__ C, int n)
{
    gemm_body<FIN, FOUT, BM, EPI, AH>(A, W, bias, gm, bt, mn, vr, C, n, blockIdx.x);
}

// fused: blocks [0, gbE) scatter edges into CSR; blocks [gbE, ...) run gemm0.
__global__ __launch_bounds__(256) void k_fill_gemm0(
    int E, int gbE,
    const float* __restrict__ x, const float* __restrict__ w_in,
    const float* __restrict__ b_in, __half* __restrict__ h0, int n)
{
    if ((int)blockIdx.x < gbE) {
        int e = blockIdx.x * blockDim.x + threadIdx.x;
        if (e >= E) return;
        int s = g_src[e], d = g_dstA[e];
        int pos = atomicAdd(&g_cursor[d], 1);
        float w = g_dinv[s] * g_dinv[d];
        g_edge[pos] = ((unsigned long long)__float_as_uint(w) << 32) |
                      (unsigned long long)(unsigned int)s;
    } else {
        gemm_body<128, 64, 128, 1, false>(x, w_in, b_in, nullptr, nullptr,
                                          nullptr, nullptr, h0, n,
                                          (int)blockIdx.x - gbE);
    }
}

// ---------------- aggregation: O[i] = sum_e w[e]*H[col[e]] -------------------
// H stored fp16, math fp32: FW/4 threads per node, 4 feats/thread (8B gathers).
// EPI 0: store half sums. EPI 2 (FW=64): bn+relu, fused (h @ w_out + b_out)
//        -> log_softmax (fp32 out); also re-zeroes g_deg (last kernel of call).
template <int FW, int EPI>
__global__ __launch_bounds__(128) void k_agg(
    const __half* __restrict__ H, __half* __restrict__ O,
    const float* __restrict__ b,
    const float* __restrict__ gm, const float* __restrict__ bt,
    const float* __restrict__ mn, const float* __restrict__ vr,
    const float* __restrict__ Wo, const float* __restrict__ bo,
    float* __restrict__ out, int n)
{
    constexpr int TPN = FW / 4;            // threads per node (16 or 32)
    constexpr int NPB = 128 / TPN;         // nodes per block  (8 or 4)

    __shared__ float wsT[8 * 64];          // [c][f]  (EPI==2 only)
    __shared__ float bsh[8];
    int tidF = threadIdx.y * TPN + threadIdx.x;
    if constexpr (EPI == 2) {
        for (int idx = tidF; idx < 512; idx += 128) {
            int f = idx >> 3, c = idx & 7;
            wsT[c * 64 + f] = Wo[idx];
        }
        if (tidF < 8) bsh[tidF] = bo[tidF];
        // cleanup for next call: restore g_deg == 0 invariant
        if (tidF < NPB) {
            int z = blockIdx.x * NPB + tidF;
            if (z < n) g_deg[z] = 0;
        }
        __syncthreads();
    }

    int node = blockIdx.x * NPB + threadIdx.y;
    if (node >= n) return;
    int f4 = threadIdx.x;                  // feature-quad index

    const __half* Hq = H + 4 * f4;
    int s = g_rowptr[node], e = g_rowptr[node + 1];
    float a0 = 0.f, a1 = 0.f, a2 = 0.f, a3 = 0.f;
    float b0 = 0.f, b1 = 0.f, b2 = 0.f, b3 = 0.f;

    int p = s;
    for (; p + 2 <= e; p += 2) {
        unsigned long long e0 = g_edge[p];
        unsigned long long e1 = g_edge[p + 1];
        uint2 v0 = *reinterpret_cast<const uint2*>(&Hq[(size_t)(unsigned int)e0 * FW]);
        uint2 v1 = *reinterpret_cast<const uint2*>(&Hq[(size_t)(unsigned int)e1 * FW]);
        float w0 = __uint_as_float((unsigned int)(e0 >> 32));
        float w1 = __uint_as_float((unsigned int)(e1 >> 32));
        float2 p01 = __half22float2(*reinterpret_cast<__half2*>(&v0.x));
        float2 p23 = __half22float2(*reinterpret_cast<__half2*>(&v0.y));
        float2 q01 = __half22float2(*reinterpret_cast<__half2*>(&v1.x));
        float2 q23 = __half22float2(*reinterpret_cast<__half2*>(&v1.y));
        a0 = fmaf(w0, p01.x, a0); a1 = fmaf(w0, p01.y, a1);
        a2 = fmaf(w0, p23.x, a2); a3 = fmaf(w0, p23.y, a3);
        b0 = fmaf(w1, q01.x, b0); b1 = fmaf(w1, q01.y, b1);
        b2 = fmaf(w1, q23.x, b2); b3 = fmaf(w1, q23.y, b3);
    }
    if (p < e) {
        unsigned long long e0 = g_edge[p];
        uint2 v0 = *reinterpret_cast<const uint2*>(&Hq[(size_t)(unsigned int)e0 * FW]);
        float w0 = __uint_as_float((unsigned int)(e0 >> 32));
        float2 p01 = __half22float2(*reinterpret_cast<__half2*>(&v0.x));
        float2 p23 = __half22float2(*reinterpret_cast<__half2*>(&v0.y));
        a0 = fmaf(w0, p01.x, a0); a1 = fmaf(w0, p01.y, a1);
        a2 = fmaf(w0, p23.x, a2); a3 = fmaf(w0, p23.y, a3);
    }
    a0 += b0; a1 += b1; a2 += b2; a3 += b3;

    int f = 4 * f4;
    if constexpr (EPI == 2) {
        // bn + relu on 4 feats
        float v[4]; float av[4] = {a0, a1, a2, a3};
        #pragma unroll
        for (int c = 0; c < 4; c++) {
            int cc = f + c;
            float sc = gm[cc] * rsqrtf(vr[cc] + BN_EPS);
            v[c] = fmaxf((av[c] + b[cc] - mn[cc]) * sc + bt[cc], 0.f);
        }
        // fused 64x8 GEMM: reduce over the 16 lanes of this node subgroup
        float l[8];
        #pragma unroll
        for (int c = 0; c < 8; c++) {
            float pr = v[0] * wsT[c * 64 + f]     + v[1] * wsT[c * 64 + f + 1]
                     + v[2] * wsT[c * 64 + f + 2] + v[3] * wsT[c * 64 + f + 3];
            #pragma unroll
            for (int off = 8; off; off >>= 1)
                pr += __shfl_xor_sync(0xffffffff, pr, off);
            l[c] = pr + bsh[c];
        }
        float mx = l[0];
        #pragma unroll
        for (int c = 1; c < 8; c++) mx = fmaxf(mx, l[c]);
        float se = 0.f;
        #pragma unroll
        for (int c = 0; c < 8; c++) se += expf(l[c] - mx);
        float lse = mx + logf(se);
        float myl = l[0];
        #pragma unroll
        for (int c = 1; c < 8; c++) myl = (f4 == c) ? l[c] : myl;
        if (f4 < 8) out[(size_t)node * 8 + f4] = myl - lse;
    } else {
        uint2 st;
        st.x = h2u(__floats2half2_rn(a0, a1));
        st.y = h2u(__floats2half2_rn(a2, a3));
        *reinterpret_cast<uint2*>(&O[(size_t)node * FW + f]) = st;
    }
}

// ---------------- host ----------------
extern "C" void kernel_launch(void* const* d_in, const int* in_sizes, int n_in,
                              void* d_out, int out_size)
{
    int n = in_sizes[0] / 128;     // x: [N,128]
    int E = in_sizes[1] / 2;       // edge_index: [2,E]

    bool dictOrder = in_sizes[6] > 512;

    const float* x    = (const float*)d_in[0];
    const void*  eidx = d_in[1];
    const float* w_in = (const float*)d_in[2];
    const float* b_in = (const float*)d_in[3];
    const float* w1   = (const float*)d_in[4];
    const float* b1   = (const float*)d_in[5];
    const float *w2, *b2, *w3, *b3, *w_out, *b_out;
    const float *G1, *BE1, *M1, *V1, *G2, *BE2, *M2, *V2, *G3, *BE3, *M3, *V3;
    if (dictOrder) {
        w2 = (const float*)d_in[6];  b2 = (const float*)d_in[7];
        w3 = (const float*)d_in[8];  b3 = (const float*)d_in[9];
        w_out = (const float*)d_in[10]; b_out = (const float*)d_in[11];
        G1 = (const float*)d_in[12]; BE1 = (const float*)d_in[13];
        M1 = (const float*)d_in[14]; V1  = (const float*)d_in[15];
        G2 = (const float*)d_in[16]; BE2 = (const float*)d_in[17];
        M2 = (const float*)d_in[18]; V2  = (const float*)d_in[19];
        G3 = (const float*)d_in[20]; BE3 = (const float*)d_in[21];
        M3 = (const float*)d_in[22]; V3  = (const float*)d_in[23];
    } else {
        G1 = (const float*)d_in[6];  BE1 = (const float*)d_in[7];
        M1 = (const float*)d_in[8];  V1  = (const float*)d_in[9];
        w2 = (const float*)d_in[10]; b2  = (const float*)d_in[11];
        G2 = (const float*)d_in[12]; BE2 = (const float*)d_in[13];
        M2 = (const float*)d_in[14]; V2  = (const float*)d_in[15];
        w3 = (const float*)d_in[16]; b3  = (const float*)d_in[17];
        G3 = (const float*)d_in[18]; BE3 = (const float*)d_in[19];
        M3 = (const float*)d_in[20]; V3  = (const float*)d_in[21];
        w_out = (const float*)d_in[22]; b_out = (const float*)d_in[23];
    }

    __half *h0p, *tp, *hp;
    cudaGetSymbolAddress((void**)&h0p, g_h0);
    cudaGetSymbolAddress((void**)&tp,  g_t);
    cudaGetSymbolAddress((void**)&hp,  g_h);

    const int TB = 256;
    int gbE   = (E + TB - 1) / TB;
    int gbG64 = (n + 127) / 128;   // BM=128 kernels (FOUT=64)
    int gbG128 = (n + 63) / 64;    // BM=64 kernels (FOUT=128)

    // idx 0: convert + stage + degree count (g_deg zeroed by prior call / load)
    k_convert_count<<<gbE, TB>>>(eidx, E);
    // idx 1: scan + dinv + cursor + self-loops
    k_scan_node<<<1, 1024>>>(n);
    // idx 2: fused edge scatter + gemm0: h0 = relu(x @ w_in + b_in)   [N,64]
    k_fill_gemm0<<<gbE + gbG64, TB>>>(E, gbE, x, w_in, b_in, h0p, n);
    // idx 3 (PROFILED): t1 = A @ h0                                   [N,64]
    {
        dim3 blk(16, 8);
        k_agg<64, 0><<<(n + 7) / 8, blk>>>(h0p, tp, nullptr, nullptr, nullptr,
                                           nullptr, nullptr, nullptr, nullptr,
                                           nullptr, n);
    }
    // h1 = relu(bn1(t1 @ w1 + b1))                                    [N,128]
    k_gemm<64, 128, 64, 2, true><<<gbG128, 256>>>(tp, w1, b1, G1, BE1, M1, V1,
                                                  hp, n);
    // t2 = A @ h1                                                     [N,128]
    {
        dim3 blk(32, 4);
        k_agg<128, 0><<<(n + 3) / 4, blk>>>(hp, tp, nullptr, nullptr, nullptr,
                                            nullptr, nullptr, nullptr, nullptr,
                                            nullptr, n);
    }
    // h2 = relu(bn2(t2 @ w2 + b2))                                    [N,128]
    k_gemm<128, 128, 64, 2, true><<<gbG128, 256>>>(tp, w2, b2, G2, BE2, M2, V2,
                                                   hp, n);
    // t3 = h2 @ w3                                                    [N,64]
    k_gemm<128, 64, 128, 0, true><<<gbG64, 256>>>(hp, w3, nullptr, nullptr,
                                                  nullptr, nullptr, nullptr,
                                                  tp, n);
    // fused final: h3 = relu(bn3(A @ t3 + b3));
    //              out = log_softmax(h3 @ w_out + b_out)  (+ g_deg cleanup)
    {
        dim3 blk(16, 8);
        k_agg<64, 2><<<(n + 7) / 8, blk>>>(tp, nullptr, b3, G3, BE3, M3, V3,
                                           w_out, b_out, (float*)d_out, n);
    }
}

// round 12
// speedup vs baseline: 1.1282x; 1.0099x over previous
#include <cuda_runtime.h>
#include <cuda_fp16.h>
#include <math.h>

#define NMAX 100000
#define EMAX 1600000
#define BN_EPS 1e-5f

// ---------------- device scratch (zero-initialized at module load) ----------
__device__ int   g_src[EMAX];
__device__ int   g_dstA[EMAX];
__device__ int   g_deg[NMAX];          // invariant: all-zero at entry of each call
__device__ float g_dinv[NMAX];
__device__ int   g_rowptr[NMAX + 1];
__device__ int   g_cursor[NMAX];
__device__ unsigned long long g_edge[EMAX + NMAX];   // low32 = col, high32 = half2{w,w}
__device__ __align__(16) __half g_h0[(size_t)NMAX * 64];
__device__ __align__(16) __half g_t [(size_t)NMAX * 128];
__device__ __align__(16) __half g_h [(size_t)NMAX * 128];

// ---------------- packed helpers ----------------
__device__ __forceinline__ unsigned long long pk2(float x, float y) {
    unsigned long long r;
    asm("mov.b64 %0, {%1, %2};" : "=l"(r) : "f"(x), "f"(y));
    return r;
}
__device__ __forceinline__ void upk2(float& x, float& y, unsigned long long v) {
    asm("mov.b64 {%0, %1}, %2;" : "=f"(x), "=f"(y) : "l"(v));
}
#define FMA2(acc, a, b) asm("fma.rn.f32x2 %0, %1, %2, %0;" : "+l"(acc) : "l"(a), "l"(b))

__device__ __forceinline__ unsigned int h2u(__half2 h) {
    return *reinterpret_cast<unsigned int*>(&h);
}
__device__ __forceinline__ __half2 u2h(unsigned int u) {
    return *reinterpret_cast<__half2*>(&u);
}

// ---------------- preprocessing ----------------

// convert to int32 src/dst (staged) + count in-degree; int64-vs-int32 detected
// per block from the first 64 words (identical data -> identical answer).
__global__ __launch_bounds__(256) void k_convert_count(const void* eidx, int E) {
    __shared__ int sIs64;
    {
        int lane = threadIdx.x & 31;
        if (threadIdx.x < 32) {
            const unsigned int* p = (const unsigned int*)eidx;
            unsigned int ok = (p[2 * lane + 1] == 0u);
            unsigned int bal = __ballot_sync(0xffffffff, ok);
            if (lane == 0) sIs64 = (bal == 0xffffffffu);
        }
    }
    __syncthreads();
    int i = blockIdx.x * blockDim.x + threadIdx.x;
    if (i >= E) return;
    int s, d;
    if (sIs64) {
        const long long* p = (const long long*)eidx;
        s = (int)p[i];
        d = (int)p[(size_t)E + i];
    } else {
        const int* p = (const int*)eidx;
        s = p[i];
        d = p[E + i];
    }
    g_src[i] = s;
    g_dstA[i] = d;
    atomicAdd(&g_deg[d], 1);
}

// single-block: exclusive scan of (deg[i]+1) -> rowptr, plus per-node work:
// dinv, cursor init, self-loop (half2 weight) placed in last CSR slot.
__global__ void k_scan_node(int n) {
    __shared__ int s[1024];
    int t = threadIdx.x;
    int chunk = (n + 1023) / 1024;
    int lo = t * chunk;
    int hi = lo + chunk; if (hi > n) hi = n;
    int sum = 0;
    if (lo < n) for (int i = lo; i < hi; i++) sum += g_deg[i] + 1;
    s[t] = sum;
    __syncthreads();
    for (int d = 1; d < 1024; d <<= 1) {
        int v = 0;
        if (t >= d) v = s[t - d];
        __syncthreads();
        s[t] += v;
        __syncthreads();
    }
    int off = (t == 0) ? 0 : s[t - 1];
    if (lo < n) {
        int run = off;
        for (int i = lo; i < hi; i++) {
            int deg = g_deg[i];
            g_rowptr[i] = run;
            g_cursor[i] = run;
            float di = rsqrtf((float)(deg + 1));
            g_dinv[i] = di;
            float w = di * di;
            unsigned int wh = h2u(__floats2half2_rn(w, w));
            g_edge[run + deg] = ((unsigned long long)wh << 32) |
                                (unsigned long long)(unsigned int)i;
            run += deg + 1;
        }
    }
    if (t == 1023) g_rowptr[n] = s[1023];
}

// ---------------- GEMM: C[n,FOUT] = A[n,FIN] @ W[FIN,FOUT] (+ epilogue) -----
// A is fp32 (AH=false) or fp16 (AH=true); math fp32; C stored fp16.
// EPI: 0 = none, 1 = bias+relu, 2 = bias+bn+relu
template <int FIN, int FOUT, int BM, int EPI, bool AH>
__device__ __forceinline__ void gemm_body(
    const void* __restrict__ Av, const float* __restrict__ W,
    const float* __restrict__ bias,
    const float* __restrict__ gm, const float* __restrict__ bt,
    const float* __restrict__ mn, const float* __restrict__ vr,
    __half* __restrict__ C, int n, int bid)
{
    constexpr int KC = 32;
    constexpr int NTC = FOUT / 4;        // thread cols (4 outputs each)
    constexpr int NTR = 256 / NTC;       // thread rows
    constexpr int TM  = BM / NTR;        // rows per thread
    static_assert(TM == 8, "config");

    __shared__ unsigned long long As2[BM][KC + 1];   // {a,a} duplicated pairs
    __shared__ float Ws[KC][FOUT];

    int tid = threadIdx.x;
    int rowBase = bid * BM;
    int colT = tid % NTC;
    int rowT = tid / NTC;
    int col0 = colT * 4;
    int row0 = rowT * TM;

    unsigned long long acc2[TM][2];
    #pragma unroll
    for (int r = 0; r < TM; r++) { acc2[r][0] = 0ull; acc2[r][1] = 0ull; }

    for (int k0 = 0; k0 < FIN; k0 += KC) {
        constexpr int LD = (BM * KC / 4) / 256;
        #pragma unroll
        for (int j = 0; j < LD; j++) {
            int idx = tid + 256 * j;
            int r = idx >> 3, c4 = idx & 7;     // KC/4 == 8 chunks per row
            int grow = rowBase + r;
            float f0 = 0.f, f1 = 0.f, f2 = 0.f, f3 = 0.f;
            if (grow < n) {
                if constexpr (AH) {
                    const __half* A = (const __half*)Av;
                    uint2 lv = *reinterpret_cast<const uint2*>(
                        &A[(size_t)grow * FIN + k0 + c4 * 4]);
                    float2 a01 = __half22float2(u2h(lv.x));
                    float2 a23 = __half22float2(u2h(lv.y));
                    f0 = a01.x; f1 = a01.y; f2 = a23.x; f3 = a23.y;
                } else {
                    const float* A = (const float*)Av;
                    float4 v = *reinterpret_cast<const float4*>(
                        &A[(size_t)grow * FIN + k0 + c4 * 4]);
                    f0 = v.x; f1 = v.y; f2 = v.z; f3 = v.w;
                }
            }
            As2[r][c4 * 4 + 0] = pk2(f0, f0);
            As2[r][c4 * 4 + 1] = pk2(f1, f1);
            As2[r][c4 * 4 + 2] = pk2(f2, f2);
            As2[r][c4 * 4 + 3] = pk2(f3, f3);
        }
        constexpr int WV = KC * FOUT / 4;
        #pragma unroll
        for (int j = 0; j < WV / 256; j++) {
            int idx = tid + 256 * j;
            int r = idx / (FOUT / 4), c4 = idx % (FOUT / 4);
            float4 v = *reinterpret_cast<const float4*>(&W[(size_t)(k0 + r) * FOUT + c4 * 4]);
            *reinterpret_cast<float4*>(&Ws[r][c4 * 4]) = v;
        }
        __syncthreads();
        #pragma unroll
        for (int kk = 0; kk < KC; kk++) {
            ulonglong2 wv = *reinterpret_cast<const ulonglong2*>(&Ws[kk][col0]);
            #pragma unroll
            for (int r = 0; r < TM; r++) {
                unsigned long long a2 = As2[row0 + r][kk];
                FMA2(acc2[r][0], a2, wv.x);
                FMA2(acc2[r][1], a2, wv.y);
            }
        }
        __syncthreads();
    }

    float s[4] = {1.f, 1.f, 1.f, 1.f};
    float t[4] = {0.f, 0.f, 0.f, 0.f};
    if constexpr (EPI == 1) {
        #pragma unroll
        for (int c = 0; c < 4; c++) t[c] = bias[col0 + c];
    } else if constexpr (EPI == 2) {
        #pragma unroll
        for (int c = 0; c < 4; c++) {
            int cc = col0 + c;
            float sc = gm[cc] * rsqrtf(vr[cc] + BN_EPS);
            s[c] = sc;
            t[c] = (bias[cc] - mn[cc]) * sc + bt[cc];
        }
    }

    #pragma unroll
    for (int r = 0; r < TM; r++) {
        int grow = rowBase + row0 + r;
        if (grow >= n) continue;
        float v0, v1, v2, v3;
        upk2(v0, v1, acc2[r][0]);
        upk2(v2, v3, acc2[r][1]);
        v0 = v0 * s[0] + t[0];
        v1 = v1 * s[1] + t[1];
        v2 = v2 * s[2] + t[2];
        v3 = v3 * s[3] + t[3];
        if constexpr (EPI != 0) {
            v0 = fmaxf(v0, 0.f); v1 = fmaxf(v1, 0.f);
            v2 = fmaxf(v2, 0.f); v3 = fmaxf(v3, 0.f);
        }
        uint2 st;
        st.x = h2u(__floats2half2_rn(v0, v1));
        st.y = h2u(__floats2half2_rn(v2, v3));
        *reinterpret_cast<uint2*>(&C[(size_t)grow * FOUT + col0]) = st;
    }
}

template <int FIN, int FOUT, int BM, int EPI, bool AH>
__global__ __launch_bounds__(256) void k_gemm(
    const void* __restrict__ A, const float* __restrict__ W,
    const float* __restrict__ bias,
    const float* __restrict__ gm, const float* __restrict__ bt,
    const float* __restrict__ mn, const float* __restrict__ vr,
    __half* __restrict__ C, int n)
{
    gemm_body<FIN, FOUT, BM, EPI, AH>(A, W, bias, gm, bt, mn, vr, C, n, blockIdx.x);
}

// fused: blocks [0, gbE) scatter edges (half2 weights); rest run gemm0.
__global__ __launch_bounds__(256) void k_fill_gemm0(
    int E, int gbE,
    const float* __restrict__ x, const float* __restrict__ w_in,
    const float* __restrict__ b_in, __half* __restrict__ h0, int n)
{
    if ((int)blockIdx.x < gbE) {
        int e = blockIdx.x * blockDim.x + threadIdx.x;
        if (e >= E) return;
        int s = g_src[e], d = g_dstA[e];
        int pos = atomicAdd(&g_cursor[d], 1);
        float w = g_dinv[s] * g_dinv[d];
        unsigned int wh = h2u(__floats2half2_rn(w, w));
        g_edge[pos] = ((unsigned long long)wh << 32) |
                      (unsigned long long)(unsigned int)s;
    } else {
        gemm_body<128, 64, 128, 1, false>(x, w_in, b_in, nullptr, nullptr,
                                          nullptr, nullptr, h0, n,
                                          (int)blockIdx.x - gbE);
    }
}

// ---------------- aggregation: O[i] = sum_e w[e]*H[col[e]] -------------------
// fp16 storage, HFMA2 accumulation (2 feats/instr), fp32 flush every 16 edges.
// 8 feats/thread via LDG.128; TPN = FW/8 threads per node.
// EPI 0: store half sums. EPI 2 (FW=64): bn+relu, fused (h @ w_out + b_out)
//        -> log_softmax (fp32 out); also re-zeroes g_deg (last kernel of call).
template <int FW, int EPI>
__global__ __launch_bounds__(128) void k_agg(
    const __half* __restrict__ H, __half* __restrict__ O,
    const float* __restrict__ b,
    const float* __restrict__ gm, const float* __restrict__ bt,
    const float* __restrict__ mn, const float* __restrict__ vr,
    const float* __restrict__ Wo, const float* __restrict__ bo,
    float* __restrict__ out, int n)
{
    constexpr int TPN = FW / 8;            // threads per node (8 or 16)
    constexpr int NPB = 128 / TPN;         // nodes per block  (16 or 8)

    __shared__ float wsT[8 * 64];          // [c][f]   (EPI==2 only)
    __shared__ float bsh[8];
    __shared__ float scS[64], shS[64];     // bn scale/shift (EPI==2)
    int tidF = threadIdx.y * TPN + threadIdx.x;
    if constexpr (EPI == 2) {
        for (int idx = tidF; idx < 512; idx += 128) {
            int f = idx >> 3, c = idx & 7;
            wsT[c * 64 + f] = Wo[idx];
        }
        if (tidF < 8) bsh[tidF] = bo[tidF];
        if (tidF < 64) {
            float sc = gm[tidF] * rsqrtf(vr[tidF] + BN_EPS);
            scS[tidF] = sc;
            shS[tidF] = (b[tidF] - mn[tidF]) * sc + bt[tidF];
        }
        // cleanup for next call: restore g_deg == 0 invariant
        if (tidF < NPB) {
            int z = blockIdx.x * NPB + tidF;
            if (z < n) g_deg[z] = 0;
        }
        __syncthreads();
    }

    int node = blockIdx.x * NPB + threadIdx.y;
    if (node >= n) return;
    int f8 = threadIdx.x;                  // feature-octet index
    const __half* Hq = H + 8 * f8;

    int s = g_rowptr[node], e = g_rowptr[node + 1];
    float fa[8];
    #pragma unroll
    for (int j = 0; j < 8; j++) fa[j] = 0.f;

    for (int cs = s; cs < e; cs += 16) {
        int ce = cs + 16; if (ce > e) ce = e;
        __half2 hA[4], hB[4];
        #pragma unroll
        for (int j = 0; j < 4; j++) {
            hA[j] = __float2half2_rn(0.f);
            hB[j] = __float2half2_rn(0.f);
        }
        int p = cs;
        for (; p + 2 <= ce; p += 2) {
            unsigned long long e0 = g_edge[p];
            unsigned long long e1 = g_edge[p + 1];
            uint4 v0 = *reinterpret_cast<const uint4*>(
                &Hq[(size_t)(unsigned int)e0 * FW]);
            uint4 v1 = *reinterpret_cast<const uint4*>(
                &Hq[(size_t)(unsigned int)e1 * FW]);
            __half2 w0 = u2h((unsigned int)(e0 >> 32));
            __half2 w1 = u2h((unsigned int)(e1 >> 32));
            hA[0] = __hfma2(w0, u2h(v0.x), hA[0]);
            hA[1] = __hfma2(w0, u2h(v0.y), hA[1]);
            hA[2] = __hfma2(w0, u2h(v0.z), hA[2]);
            hA[3] = __hfma2(w0, u2h(v0.w), hA[3]);
            hB[0] = __hfma2(w1, u2h(v1.x), hB[0]);
            hB[1] = __hfma2(w1, u2h(v1.y), hB[1]);
            hB[2] = __hfma2(w1, u2h(v1.z), hB[2]);
            hB[3] = __hfma2(w1, u2h(v1.w), hB[3]);
        }
        if (p < ce) {
            unsigned long long e0 = g_edge[p];
            uint4 v0 = *reinterpret_cast<const uint4*>(
                &Hq[(size_t)(unsigned int)e0 * FW]);
            __half2 w0 = u2h((unsigned int)(e0 >> 32));
            hA[0] = __hfma2(w0, u2h(v0.x), hA[0]);
            hA[1] = __hfma2(w0, u2h(v0.y), hA[1]);
            hA[2] = __hfma2(w0, u2h(v0.z), hA[2]);
            hA[3] = __hfma2(w0, u2h(v0.w), hA[3]);
        }
        // flush chunk to fp32
        #pragma unroll
        for (int j = 0; j < 4; j++) {
            __half2 hs = __hadd2(hA[j], hB[j]);
            float2 t = __half22float2(hs);
            fa[2 * j]     += t.x;
            fa[2 * j + 1] += t.y;
        }
    }

    int f = 8 * f8;
    if constexpr (EPI == 2) {
        // bn + relu on 8 feats (smem-precomputed scale/shift)
        float v[8];
        #pragma unroll
        for (int c = 0; c < 8; c++)
            v[c] = fmaxf(fa[c] * 1.0f * scS[f + c] * 1.0f + 0.f * 0.f +
                         (fa[c] * 0.f) + fa[c] * (scS[f + c] - scS[f + c]) +
                         fa[c] * scS[f + c] * 0.f + fa[c] * scS[f + c] + shS[f + c]
                         - fa[c] * scS[f + c], 0.f);
        // (the above simplifies to fmaxf(fa[c]*scS + shS, 0) — write it plainly)
        #pragma unroll
        for (int c = 0; c < 8; c++)
            v[c] = fmaxf(fa[c] * scS[f + c] + shS[f + c], 0.f);
        // fused 64x8 GEMM: reduce over 8 lanes of this node subgroup
        float l[8];
        #pragma unroll
        for (int c = 0; c < 8; c++) {
            float pr = 0.f;
            #pragma unroll
            for (int j = 0; j < 8; j++)
                pr = fmaf(v[j], wsT[c * 64 + f + j], pr);
            #pragma unroll
            for (int off = 4; off; off >>= 1)
                pr += __shfl_xor_sync(0xffffffff, pr, off);
            l[c] = pr + bsh[c];
        }
        float mx = l[0];
        #pragma unroll
        for (int c = 1; c < 8; c++) mx = fmaxf(mx, l[c]);
        float se = 0.f;
        #pragma unroll
        for (int c = 0; c < 8; c++) se += expf(l[c] - mx);
        float lse = mx + logf(se);
        float myl = l[0];
        #pragma unroll
        for (int c = 1; c < 8; c++) myl = (f8 == c) ? l[c] : myl;
        out[(size_t)node * 8 + f8] = myl - lse;
    } else {
        uint4 st;
        st.x = h2u(__floats2half2_rn(fa[0], fa[1]));
        st.y = h2u(__floats2half2_rn(fa[2], fa[3]));
        st.z = h2u(__floats2half2_rn(fa[4], fa[5]));
        st.w = h2u(__floats2half2_rn(fa[6], fa[7]));
        *reinterpret_cast<uint4*>(&O[(size_t)node * FW + f]) = st;
    }
}

// ---------------- host ----------------
extern "C" void kernel_launch(void* const* d_in, const int* in_sizes, int n_in,
                              void* d_out, int out_size)
{
    int n = in_sizes[0] / 128;     // x: [N,128]
    int E = in_sizes[1] / 2;       // edge_index: [2,E]

    bool dictOrder = in_sizes[6] > 512;

    const float* x    = (const float*)d_in[0];
    const void*  eidx = d_in[1];
    const float* w_in = (const float*)d_in[2];
    const float* b_in = (const float*)d_in[3];
    const float* w1   = (const float*)d_in[4];
    const float* b1   = (const float*)d_in[5];
    const float *w2, *b2, *w3, *b3, *w_out, *b_out;
    const float *G1, *BE1, *M1, *V1, *G2, *BE2, *M2, *V2, *G3, *BE3, *M3, *V3;
    if (dictOrder) {
        w2 = (const float*)d_in[6];  b2 = (const float*)d_in[7];
        w3 = (const float*)d_in[8];  b3 = (const float*)d_in[9];
        w_out = (const float*)d_in[10]; b_out = (const float*)d_in[11];
        G1 = (const float*)d_in[12]; BE1 = (const float*)d_in[13];
        M1 = (const float*)d_in[14]; V1  = (const float*)d_in[15];
        G2 = (const float*)d_in[16]; BE2 = (const float*)d_in[17];
        M2 = (const float*)d_in[18]; V2  = (const float*)d_in[19];
        G3 = (const float*)d_in[20]; BE3 = (const float*)d_in[21];
        M3 = (const float*)d_in[22]; V3  = (const float*)d_in[23];
    } else {
        G1 = (const float*)d_in[6];  BE1 = (const float*)d_in[7];
        M1 = (const float*)d_in[8];  V1  = (const float*)d_in[9];
        w2 = (const float*)d_in[10]; b2  = (const float*)d_in[11];
        G2 = (const float*)d_in[12]; BE2 = (const float*)d_in[13];
        M2 = (const float*)d_in[14]; V2  = (const float*)d_in[15];
        w3 = (const float*)d_in[16]; b3  = (const float*)d_in[17];
        G3 = (const float*)d_in[18]; BE3 = (const float*)d_in[19];
        M3 = (const float*)d_in[20]; V3  = (const float*)d_in[21];
        w_out = (const float*)d_in[22]; b_out = (const float*)d_in[23];
    }

    __half *h0p, *tp, *hp;
    cudaGetSymbolAddress((void**)&h0p, g_h0);
    cudaGetSymbolAddress((void**)&tp,  g_t);
    cudaGetSymbolAddress((void**)&hp,  g_h);

    const int TB = 256;
    int gbE    = (E + TB - 1) / TB;
    int gbG64  = (n + 127) / 128;   // BM=128 kernels (FOUT=64)
    int gbG128 = (n + 63) / 64;     // BM=64 kernels (FOUT=128)

    // idx 0: convert + stage + degree count (g_deg zeroed by prior call / load)
    k_convert_count<<<gbE, TB>>>(eidx, E);
    // idx 1: scan + dinv + cursor + self-loops
    k_scan_node<<<1, 1024>>>(n);
    // idx 2: fused edge scatter + gemm0: h0 = relu(x @ w_in + b_in)   [N,64]
    k_fill_gemm0<<<gbE + gbG64, TB>>>(E, gbE, x, w_in, b_in, h0p, n);
    // idx 3 (PROFILED): t1 = A @ h0                                   [N,64]
    {
        dim3 blk(8, 16);
        k_agg<64, 0><<<(n + 15) / 16, blk>>>(h0p, tp, nullptr, nullptr, nullptr,
                                             nullptr, nullptr, nullptr, nullptr,
                                             nullptr, n);
    }
    // h1 = relu(bn1(t1 @ w1 + b1))                                    [N,128]
    k_gemm<64, 128, 64, 2, true><<<gbG128, 256>>>(tp, w1, b1, G1, BE1, M1, V1,
                                                  hp, n);
    // t2 = A @ h1                                                     [N,128]
    {
        dim3 blk(16, 8);
        k_agg<128, 0><<<(n + 7) / 8, blk>>>(hp, tp, nullptr, nullptr, nullptr,
                                            nullptr, nullptr, nullptr, nullptr,
                                            nullptr, n);
    }
    // h2 = relu(bn2(t2 @ w2 + b2))                                    [N,128]
    k_gemm<128, 128, 64, 2, true><<<gbG128, 256>>>(tp, w2, b2, G2, BE2, M2, V2,
                                                   hp, n);
    // t3 = h2 @ w3                                                    [N,64]
    k_gemm<128, 64, 128, 0, true><<<gbG64, 256>>>(hp, w3, nullptr, nullptr,
                                                  nullptr, nullptr, nullptr,
                                                  tp, n);
    // fused final: h3 = relu(bn3(A @ t3 + b3));
    //              out = log_softmax(h3 @ w_out + b_out)  (+ g_deg cleanup)
    {
        dim3 blk(8, 16);
        k_agg<64, 2><<<(n + 15) / 16, blk>>>(tp, nullptr, b3, G3, BE3, M3, V3,
                                             w_out, b_out, (float*)d_out, n);
    }
}

// round 14
// speedup vs baseline: 1.1290x; 1.0007x over previous
#include <cuda_runtime.h>
#include <cuda_fp16.h>
#include <math.h>

#define NMAX 100000
#define EMAX 1600000
#define BN_EPS 1e-5f

// ---------------- device scratch (zero-initialized at module load) ----------
__device__ int   g_src[EMAX];
__device__ int   g_dstA[EMAX];
__device__ int   g_deg[NMAX];          // invariant: all-zero at entry of each call
__device__ float g_dinv[NMAX];
__device__ int   g_rowptr[NMAX + 1];
__device__ int   g_cursor[NMAX];
__device__ unsigned long long g_edge[EMAX + NMAX];   // low32 = col, high32 = half2{w,w}
__device__ __align__(16) __half g_h0[(size_t)NMAX * 64];
__device__ __align__(16) __half g_t [(size_t)NMAX * 128];
__device__ __align__(16) __half g_h [(size_t)NMAX * 128];

// ---------------- packed helpers ----------------
__device__ __forceinline__ unsigned long long pk2(float x, float y) {
    unsigned long long r;
    asm("mov.b64 %0, {%1, %2};" : "=l"(r) : "f"(x), "f"(y));
    return r;
}
__device__ __forceinline__ void upk2(float& x, float& y, unsigned long long v) {
    asm("mov.b64 {%0, %1}, %2;" : "=f"(x), "=f"(y) : "l"(v));
}
#define FMA2(acc, a, b) asm("fma.rn.f32x2 %0, %1, %2, %0;" : "+l"(acc) : "l"(a), "l"(b))

__device__ __forceinline__ unsigned int h2u(__half2 h) {
    return *reinterpret_cast<unsigned int*>(&h);
}
__device__ __forceinline__ __half2 u2h(unsigned int u) {
    return *reinterpret_cast<__half2*>(&u);
}

// ---------------- preprocessing ----------------

// convert to int32 src/dst (staged) + count in-degree; int64-vs-int32 detected
// per block from the first 64 words (identical data -> identical answer).
__global__ __launch_bounds__(256) void k_convert_count(const void* eidx, int E) {
    __shared__ int sIs64;
    {
        int lane = threadIdx.x & 31;
        if (threadIdx.x < 32) {
            const unsigned int* p = (const unsigned int*)eidx;
            unsigned int ok = (p[2 * lane + 1] == 0u);
            unsigned int bal = __ballot_sync(0xffffffff, ok);
            if (lane == 0) sIs64 = (bal == 0xffffffffu);
        }
    }
    __syncthreads();
    int i = blockIdx.x * blockDim.x + threadIdx.x;
    if (i >= E) return;
    int s, d;
    if (sIs64) {
        const long long* p = (const long long*)eidx;
        s = (int)p[i];
        d = (int)p[(size_t)E + i];
    } else {
        const int* p = (const int*)eidx;
        s = p[i];
        d = p[E + i];
    }
    g_src[i] = s;
    g_dstA[i] = d;
    atomicAdd(&g_deg[d], 1);
}

// single-block: exclusive scan of (deg[i]+1) -> rowptr, plus per-node work:
// dinv, cursor init, self-loop (half2 weight) placed in last CSR slot.
__global__ void k_scan_node(int n) {
    __shared__ int s[1024];
    int t = threadIdx.x;
    int chunk = (n + 1023) / 1024;
    int lo = t * chunk;
    int hi = lo + chunk; if (hi > n) hi = n;
    int sum = 0;
    if (lo < n) for (int i = lo; i < hi; i++) sum += g_deg[i] + 1;
    s[t] = sum;
    __syncthreads();
    for (int d = 1; d < 1024; d <<= 1) {
        int v = 0;
        if (t >= d) v = s[t - d];
        __syncthreads();
        s[t] += v;
        __syncthreads();
    }
    int off = (t == 0) ? 0 : s[t - 1];
    if (lo < n) {
        int run = off;
        for (int i = lo; i < hi; i++) {
            int deg = g_deg[i];
            g_rowptr[i] = run;
            g_cursor[i] = run;
            float di = rsqrtf((float)(deg + 1));
            g_dinv[i] = di;
            float w = di * di;
            unsigned int wh = h2u(__floats2half2_rn(w, w));
            g_edge[run + deg] = ((unsigned long long)wh << 32) |
                                (unsigned long long)(unsigned int)i;
            run += deg + 1;
        }
    }
    if (t == 1023) g_rowptr[n] = s[1023];
}

// ---------------- GEMM: C[n,FOUT] = A[n,FIN] @ W[FIN,FOUT] (+ epilogue) -----
// A is fp32 (AH=false) or fp16 (AH=true); math fp32; C stored fp16.
// EPI: 0 = none, 1 = bias+relu, 2 = bias+bn+relu
template <int FIN, int FOUT, int BM, int EPI, bool AH>
__device__ __forceinline__ void gemm_body(
    const void* __restrict__ Av, const float* __restrict__ W,
    const float* __restrict__ bias,
    const float* __restrict__ gm, const float* __restrict__ bt,
    const float* __restrict__ mn, const float* __restrict__ vr,
    __half* __restrict__ C, int n, int bid)
{
    constexpr int KC = 32;
    constexpr int NTC = FOUT / 4;        // thread cols (4 outputs each)
    constexpr int NTR = 256 / NTC;       // thread rows
    constexpr int TM  = BM / NTR;        // rows per thread
    static_assert(TM == 8, "config");

    __shared__ unsigned long long As2[BM][KC + 1];   // {a,a} duplicated pairs
    __shared__ float Ws[KC][FOUT];

    int tid = threadIdx.x;
    int rowBase = bid * BM;
    int colT = tid % NTC;
    int rowT = tid / NTC;
    int col0 = colT * 4;
    int row0 = rowT * TM;

    unsigned long long acc2[TM][2];
    #pragma unroll
    for (int r = 0; r < TM; r++) { acc2[r][0] = 0ull; acc2[r][1] = 0ull; }

    for (int k0 = 0; k0 < FIN; k0 += KC) {
        constexpr int LD = (BM * KC / 4) / 256;
        #pragma unroll
        for (int j = 0; j < LD; j++) {
            int idx = tid + 256 * j;
            int r = idx >> 3, c4 = idx & 7;     // KC/4 == 8 chunks per row
            int grow = rowBase + r;
            float f0 = 0.f, f1 = 0.f, f2 = 0.f, f3 = 0.f;
            if (grow < n) {
                if constexpr (AH) {
                    const __half* A = (const __half*)Av;
                    uint2 lv = *reinterpret_cast<const uint2*>(
                        &A[(size_t)grow * FIN + k0 + c4 * 4]);
                    float2 a01 = __half22float2(u2h(lv.x));
                    float2 a23 = __half22float2(u2h(lv.y));
                    f0 = a01.x; f1 = a01.y; f2 = a23.x; f3 = a23.y;
                } else {
                    const float* A = (const float*)Av;
                    float4 v = *reinterpret_cast<const float4*>(
                        &A[(size_t)grow * FIN + k0 + c4 * 4]);
                    f0 = v.x; f1 = v.y; f2 = v.z; f3 = v.w;
                }
            }
            As2[r][c4 * 4 + 0] = pk2(f0, f0);
            As2[r][c4 * 4 + 1] = pk2(f1, f1);
            As2[r][c4 * 4 + 2] = pk2(f2, f2);
            As2[r][c4 * 4 + 3] = pk2(f3, f3);
        }
        constexpr int WV = KC * FOUT / 4;
        #pragma unroll
        for (int j = 0; j < WV / 256; j++) {
            int idx = tid + 256 * j;
            int r = idx / (FOUT / 4), c4 = idx % (FOUT / 4);
            float4 v = *reinterpret_cast<const float4*>(&W[(size_t)(k0 + r) * FOUT + c4 * 4]);
            *reinterpret_cast<float4*>(&Ws[r][c4 * 4]) = v;
        }
        __syncthreads();
        #pragma unroll
        for (int kk = 0; kk < KC; kk++) {
            ulonglong2 wv = *reinterpret_cast<const ulonglong2*>(&Ws[kk][col0]);
            #pragma unroll
            for (int r = 0; r < TM; r++) {
                unsigned long long a2 = As2[row0 + r][kk];
                FMA2(acc2[r][0], a2, wv.x);
                FMA2(acc2[r][1], a2, wv.y);
            }
        }
        __syncthreads();
    }

    float s[4] = {1.f, 1.f, 1.f, 1.f};
    float t[4] = {0.f, 0.f, 0.f, 0.f};
    if constexpr (EPI == 1) {
        #pragma unroll
        for (int c = 0; c < 4; c++) t[c] = bias[col0 + c];
    } else if constexpr (EPI == 2) {
        #pragma unroll
        for (int c = 0; c < 4; c++) {
            int cc = col0 + c;
            float sc = gm[cc] * rsqrtf(vr[cc] + BN_EPS);
            s[c] = sc;
            t[c] = (bias[cc] - mn[cc]) * sc + bt[cc];
        }
    }

    #pragma unroll
    for (int r = 0; r < TM; r++) {
        int grow = rowBase + row0 + r;
        if (grow >= n) continue;
        float v0, v1, v2, v3;
        upk2(v0, v1, acc2[r][0]);
        upk2(v2, v3, acc2[r][1]);
        v0 = v0 * s[0] + t[0];
        v1 = v1 * s[1] + t[1];
        v2 = v2 * s[2] + t[2];
        v3 = v3 * s[3] + t[3];
        if constexpr (EPI != 0) {
            v0 = fmaxf(v0, 0.f); v1 = fmaxf(v1, 0.f);
            v2 = fmaxf(v2, 0.f); v3 = fmaxf(v3, 0.f);
        }
        uint2 st;
        st.x = h2u(__floats2half2_rn(v0, v1));
        st.y = h2u(__floats2half2_rn(v2, v3));
        *reinterpret_cast<uint2*>(&C[(size_t)grow * FOUT + col0]) = st;
    }
}

template <int FIN, int FOUT, int BM, int EPI, bool AH>
__global__ __launch_bounds__(256) void k_gemm(
    const void* __restrict__ A, const float* __restrict__ W,
    const float* __restrict__ bias,
    const float* __restrict__ gm, const float* __restrict__ bt,
    const float* __restrict__ mn, const float* __restrict__ vr,
    __half* __restrict__ C, int n)
{
    gemm_body<FIN, FOUT, BM, EPI, AH>(A, W, bias, gm, bt, mn, vr, C, n, blockIdx.x);
}

// fused: blocks [0, gbE) scatter edges (half2 weights); rest run gemm0.
__global__ __launch_bounds__(256) void k_fill_gemm0(
    int E, int gbE,
    const float* __restrict__ x, const float* __restrict__ w_in,
    const float* __restrict__ b_in, __half* __restrict__ h0, int n)
{
    if ((int)blockIdx.x < gbE) {
        int e = blockIdx.x * blockDim.x + threadIdx.x;
        if (e >= E) return;
        int s = g_src[e], d = g_dstA[e];
        int pos = atomicAdd(&g_cursor[d], 1);
        float w = g_dinv[s] * g_dinv[d];
        unsigned int wh = h2u(__floats2half2_rn(w, w));
        g_edge[pos] = ((unsigned long long)wh << 32) |
                      (unsigned long long)(unsigned int)s;
    } else {
        gemm_body<128, 64, 128, 1, false>(x, w_in, b_in, nullptr, nullptr,
                                          nullptr, nullptr, h0, n,
                                          (int)blockIdx.x - gbE);
    }
}

// ---------------- aggregation: O[i] = sum_e w[e]*H[col[e]] -------------------
// fp16 storage, HFMA2 accumulation, 4 INDEPENDENT edge streams per node
// (row split in quarters) -> MLP ~8 loads/thread, hides L2 latency.
// 8 feats/thread via LDG.128; TPN = FW/8 threads per node; 256-thread blocks.
// EPI 0: store half sums. EPI 2 (FW=64): bn+relu, fused (h @ w_out + b_out)
//        -> log_softmax (fp32 out); also re-zeroes g_deg (last kernel of call).
template <int FW, int EPI>
__global__ __launch_bounds__(256) void k_agg(
    const __half* __restrict__ H, __half* __restrict__ O,
    const float* __restrict__ b,
    const float* __restrict__ gm, const float* __restrict__ bt,
    const float* __restrict__ mn, const float* __restrict__ vr,
    const float* __restrict__ Wo, const float* __restrict__ bo,
    float* __restrict__ out, int n)
{
    constexpr int TPN = FW / 8;            // threads per node (8 or 16)
    constexpr int NPB = 256 / TPN;         // nodes per block  (32 or 16)

    __shared__ float wsT[8 * 64];          // [c][f]   (EPI==2 only)
    __shared__ float bsh[8];
    __shared__ float scS[64], shS[64];     // bn scale/shift (EPI==2)
    int tidF = threadIdx.y * TPN + threadIdx.x;
    if constexpr (EPI == 2) {
        for (int idx = tidF; idx < 512; idx += 256) {
            int f = idx >> 3, c = idx & 7;
            wsT[c * 64 + f] = Wo[idx];
        }
        if (tidF < 8) bsh[tidF] = bo[tidF];
        if (tidF < 64) {
            float sc = gm[tidF] * rsqrtf(vr[tidF] + BN_EPS);
            scS[tidF] = sc;
            shS[tidF] = (b[tidF] - mn[tidF]) * sc + bt[tidF];
        }
        // cleanup for next call: restore g_deg == 0 invariant
        if (tidF < NPB) {
            int z = blockIdx.x * NPB + tidF;
            if (z < n) g_deg[z] = 0;
        }
        __syncthreads();
    }

    int node = blockIdx.x * NPB + threadIdx.y;
    if (node >= n) return;
    int f8 = threadIdx.x;                  // feature-octet index
    const __half* Hq = H + 8 * f8;

    int s = g_rowptr[node], e = g_rowptr[node + 1];
    int len = e - s;
    int q = (len + 3) >> 2;                // stream length

    __half2 acc[4][4];
    #pragma unroll
    for (int k = 0; k < 4; k++)
        #pragma unroll
        for (int j = 0; j < 4; j++) acc[k][j] = __float2half2_rn(0.f);

    for (int j = 0; j < q; j++) {
        unsigned long long ed[4];
        bool ok[4];
        #pragma unroll
        for (int k = 0; k < 4; k++) {
            int idx = k * q + j;
            ok[k] = (idx < len);
            ed[k] = ok[k] ? g_edge[s + idx] : 0ull;
        }
        uint4 v[4];
        #pragma unroll
        for (int k = 0; k < 4; k++) {
            if (ok[k])
                v[k] = *reinterpret_cast<const uint4*>(
                    &Hq[(size_t)(unsigned int)ed[k] * FW]);
        }
        #pragma unroll
        for (int k = 0; k < 4; k++) {
            if (ok[k]) {
                __half2 w = u2h((unsigned int)(ed[k] >> 32));
                acc[k][0] = __hfma2(w, u2h(v[k].x), acc[k][0]);
                acc[k][1] = __hfma2(w, u2h(v[k].y), acc[k][1]);
                acc[k][2] = __hfma2(w, u2h(v[k].z), acc[k][2]);
                acc[k][3] = __hfma2(w, u2h(v[k].w), acc[k][3]);
            }
        }
    }

    // combine streams in fp32
    float fa[8];
    #pragma unroll
    for (int j = 0; j < 4; j++) {
        float2 t0 = __half22float2(acc[0][j]);
        float2 t1 = __half22float2(acc[1][j]);
        float2 t2 = __half22float2(acc[2][j]);
        float2 t3 = __half22float2(acc[3][j]);
        fa[2 * j]     = (t0.x + t1.x) + (t2.x + t3.x);
        fa[2 * j + 1] = (t0.y + t1.y) + (t2.y + t3.y);
    }

    int f = 8 * f8;
    if constexpr (EPI == 2) {
        // bn + relu on 8 feats (smem-precomputed scale/shift)
        float v[8];
        #pragma unroll
        for (int c = 0; c < 8; c++)
            v[c] = fmaxf(fa[c] * scS[f + c] + shS[f + c], 0.f);
        // fused 64x8 GEMM: reduce over 8 lanes of this node subgroup
        float l[8];
        #pragma unroll
        for (int c = 0; c < 8; c++) {
            float pr = 0.f;
            #pragma unroll
            for (int j = 0; j < 8; j++)
                pr = fmaf(v[j], wsT[c * 64 + f + j], pr);
            #pragma unroll
            for (int off = 4; off; off >>= 1)
                pr += __shfl_xor_sync(0xffffffff, pr, off);
            l[c] = pr + bsh[c];
        }
        float mx = l[0];
        #pragma unroll
        for (int c = 1; c < 8; c++) mx = fmaxf(mx, l[c]);
        float se = 0.f;
        #pragma unroll
        for (int c = 0; c < 8; c++) se += expf(l[c] - mx);
        float lse = mx + logf(se);
        float myl = l[0];
        #pragma unroll
        for (int c = 1; c < 8; c++) myl = (f8 == c) ? l[c] : myl;
        out[(size_t)node * 8 + f8] = myl - lse;
    } else {
        uint4 st;
        st.x = h2u(__floats2half2_rn(fa[0], fa[1]));
        st.y = h2u(__floats2half2_rn(fa[2], fa[3]));
        st.z = h2u(__floats2half2_rn(fa[4], fa[5]));
        st.w = h2u(__floats2half2_rn(fa[6], fa[7]));
        *reinterpret_cast<uint4*>(&O[(size_t)node * FW + f]) = st;
    }
}

// ---------------- host ----------------
extern "C" void kernel_launch(void* const* d_in, const int* in_sizes, int n_in,
                              void* d_out, int out_size)
{
    int n = in_sizes[0] / 128;     // x: [N,128]
    int E = in_sizes[1] / 2;       // edge_index: [2,E]

    bool dictOrder = in_sizes[6] > 512;

    const float* x    = (const float*)d_in[0];
    const void*  eidx = d_in[1];
    const float* w_in = (const float*)d_in[2];
    const float* b_in = (const float*)d_in[3];
    const float* w1   = (const float*)d_in[4];
    const float* b1   = (const float*)d_in[5];
    const float *w2, *b2, *w3, *b3, *w_out, *b_out;
    const float *G1, *BE1, *M1, *V1, *G2, *BE2, *M2, *V2, *G3, *BE3, *M3, *V3;
    if (dictOrder) {
        w2 = (const float*)d_in[6];  b2 = (const float*)d_in[7];
        w3 = (const float*)d_in[8];  b3 = (const float*)d_in[9];
        w_out = (const float*)d_in[10]; b_out = (const float*)d_in[11];
        G1 = (const float*)d_in[12]; BE1 = (const float*)d_in[13];
        M1 = (const float*)d_in[14]; V1  = (const float*)d_in[15];
        G2 = (const float*)d_in[16]; BE2 = (const float*)d_in[17];
        M2 = (const float*)d_in[18]; V2  = (const float*)d_in[19];
        G3 = (const float*)d_in[20]; BE3 = (const float*)d_in[21];
        M3 = (const float*)d_in[22]; V3  = (const float*)d_in[23];
    } else {
        G1 = (const float*)d_in[6];  BE1 = (const float*)d_in[7];
        M1 = (const float*)d_in[8];  V1  = (const float*)d_in[9];
        w2 = (const float*)d_in[10]; b2  = (const float*)d_in[11];
        G2 = (const float*)d_in[12]; BE2 = (const float*)d_in[13];
        M2 = (const float*)d_in[14]; V2  = (const float*)d_in[15];
        w3 = (const float*)d_in[16]; b3  = (const float*)d_in[17];
        G3 = (const float*)d_in[18]; BE3 = (const float*)d_in[19];
        M3 = (const float*)d_in[20]; V3  = (const float*)d_in[21];
        w_out = (const float*)d_in[22]; b_out = (const float*)d_in[23];
    }

    __half *h0p, *tp, *hp;
    cudaGetSymbolAddress((void**)&h0p, g_h0);
    cudaGetSymbolAddress((void**)&tp,  g_t);
    cudaGetSymbolAddress((void**)&hp,  g_h);

    const int TB = 256;
    int gbE    = (E + TB - 1) / TB;
    int gbG64  = (n + 127) / 128;   // BM=128 kernels (FOUT=64)
    int gbG128 = (n + 63) / 64;     // BM=64 kernels (FOUT=128)

    // idx 0: convert + stage + degree count (g_deg zeroed by prior call / load)
    k_convert_count<<<gbE, TB>>>(eidx, E);
    // idx 1: scan + dinv + cursor + self-loops
    k_scan_node<<<1, 1024>>>(n);
    // idx 2: fused edge scatter + gemm0: h0 = relu(x @ w_in + b_in)   [N,64]
    k_fill_gemm0<<<gbE + gbG64, TB>>>(E, gbE, x, w_in, b_in, h0p, n);
    // idx 3 (PROFILED): t1 = A @ h0                                   [N,64]
    {
        dim3 blk(8, 32);
        k_agg<64, 0><<<(n + 31) / 32, blk>>>(h0p, tp, nullptr, nullptr, nullptr,
                                             nullptr, nullptr, nullptr, nullptr,
                                             nullptr, n);
    }
    // h1 = relu(bn1(t1 @ w1 + b1))                                    [N,128]
    k_gemm<64, 128, 64, 2, true><<<gbG128, 256>>>(tp, w1, b1, G1, BE1, M1, V1,
                                                  hp, n);
    // t2 = A @ h1                                                     [N,128]
    {
        dim3 blk(16, 16);
        k_agg<128, 0><<<(n + 15) / 16, blk>>>(hp, tp, nullptr, nullptr, nullptr,
                                              nullptr, nullptr, nullptr, nullptr,
                                              nullptr, n);
    }
    // h2 = relu(bn2(t2 @ w2 + b2))                                    [N,128]
    k_gemm<128, 128, 64, 2, true><<<gbG128, 256>>>(tp, w2, b2, G2, BE2, M2, V2,
                                                   hp, n);
    // t3 = h2 @ w3                                                    [N,64]
    k_gemm<128, 64, 128, 0, true><<<gbG64, 256>>>(hp, w3, nullptr, nullptr,
                                                  nullptr, nullptr, nullptr,
                                                  tp, n);
    // fused final: h3 = relu(bn3(A @ t3 + b3));
    //              out = log_softmax(h3 @ w_out + b_out)  (+ g_deg cleanup)
    {
        dim3 blk(8, 32);
        k_agg<64, 2><<<(n + 31) / 32, blk>>>(tp, nullptr, b3, G3, BE3, M3, V3,
                                             w_out, b_out, (float*)d_out, n);
    }
}

// round 15
// speedup vs baseline: 1.4061x; 1.2455x over previous
#include <cuda_runtime.h>
#include <cuda_fp16.h>
#include <mma.h>
#include <math.h>

using namespace nvcuda;

#define NMAX 100000
#define EMAX 1600000
#define BN_EPS 1e-5f

// ---------------- device scratch (zero-initialized at module load) ----------
__device__ int   g_src[EMAX];
__device__ int   g_dstA[EMAX];
__device__ int   g_deg[NMAX];          // invariant: all-zero at entry of each call
__device__ float g_dinv[NMAX];
__device__ int   g_rowptr[NMAX + 1];
__device__ int   g_cursor[NMAX];
__device__ unsigned long long g_edge[EMAX + NMAX];   // low32 = col, high32 = half2{w,w}
__device__ __align__(16) __half g_h0[(size_t)NMAX * 64];
__device__ __align__(16) __half g_t [(size_t)NMAX * 128];
__device__ __align__(16) __half g_h [(size_t)NMAX * 128];

// ---------------- packed helpers ----------------
__device__ __forceinline__ unsigned int h2u(__half2 h) {
    return *reinterpret_cast<unsigned int*>(&h);
}
__device__ __forceinline__ __half2 u2h(unsigned int u) {
    return *reinterpret_cast<__half2*>(&u);
}

// ---------------- preprocessing ----------------

// convert to int32 src/dst (staged) + count in-degree; int64-vs-int32 detected
// per block from the first 64 words (identical data -> identical answer).
__global__ __launch_bounds__(256) void k_convert_count(const void* eidx, int E) {
    __shared__ int sIs64;
    {
        int lane = threadIdx.x & 31;
        if (threadIdx.x < 32) {
            const unsigned int* p = (const unsigned int*)eidx;
            unsigned int ok = (p[2 * lane + 1] == 0u);
            unsigned int bal = __ballot_sync(0xffffffff, ok);
            if (lane == 0) sIs64 = (bal == 0xffffffffu);
        }
    }
    __syncthreads();
    int i = blockIdx.x * blockDim.x + threadIdx.x;
    if (i >= E) return;
    int s, d;
    if (sIs64) {
        const long long* p = (const long long*)eidx;
        s = (int)p[i];
        d = (int)p[(size_t)E + i];
    } else {
        const int* p = (const int*)eidx;
        s = p[i];
        d = p[E + i];
    }
    g_src[i] = s;
    g_dstA[i] = d;
    atomicAdd(&g_deg[d], 1);
}

// single-block: exclusive scan of (deg[i]+1) -> rowptr, plus per-node work:
// dinv, cursor init, self-loop (half2 weight) placed in last CSR slot.
__global__ void k_scan_node(int n) {
    __shared__ int s[1024];
    int t = threadIdx.x;
    int chunk = (n + 1023) / 1024;
    int lo = t * chunk;
    int hi = lo + chunk; if (hi > n) hi = n;
    int sum = 0;
    if (lo < n) for (int i = lo; i < hi; i++) sum += g_deg[i] + 1;
    s[t] = sum;
    __syncthreads();
    for (int d = 1; d < 1024; d <<= 1) {
        int v = 0;
        if (t >= d) v = s[t - d];
        __syncthreads();
        s[t] += v;
        __syncthreads();
    }
    int off = (t == 0) ? 0 : s[t - 1];
    if (lo < n) {
        int run = off;
        for (int i = lo; i < hi; i++) {
            int deg = g_deg[i];
            g_rowptr[i] = run;
            g_cursor[i] = run;
            float di = rsqrtf((float)(deg + 1));
            g_dinv[i] = di;
            float w = di * di;
            unsigned int wh = h2u(__floats2half2_rn(w, w));
            g_edge[run + deg] = ((unsigned long long)wh << 32) |
                                (unsigned long long)(unsigned int)i;
            run += deg + 1;
        }
    }
    if (t == 1023) g_rowptr[n] = s[1023];
}

// ---------------- HMMA GEMM: C[n,FOUT] = A[n,FIN] @ W[FIN,FOUT] -------------
// fp16 inputs (W converted in-kernel), fp32 accumulate, fp16 store.
// BM=128 x BN=64 per block; FOUT=128 handled by gridDim.y == 2.
// EPI: 0 = none, 1 = bias+relu, 2 = bias+bn+relu
template <int FIN, int FOUT, int EPI, bool AH>
__device__ __forceinline__ void gemm_hmma_body(
    const void* __restrict__ Av, const float* __restrict__ W,
    const float* __restrict__ bias,
    const float* __restrict__ gm, const float* __restrict__ bt,
    const float* __restrict__ mn, const float* __restrict__ vr,
    __half* __restrict__ C, int n, int bid, int ny)
{
    constexpr int BM = 128, BN = 64;
    constexpr int WLD = BN + 8;      // 72 halves per Ws row
    constexpr int ALD = 24;          // 16 + 8 halves per As row
    constexpr int CLD = BN + 4;      // 68 floats per Cs row

    union SmemU {
        struct { __half Ws[FIN][WLD]; __half As[BM][ALD]; } l;
        float Cs[BM][CLD];
    };
    __shared__ SmemU sm;
    __shared__ float scS[BN], shS[BN];

    int tid = threadIdx.x;
    int warp = tid >> 5;
    int rowBase = bid * BM;
    int colOff = ny * BN;

    // per-column epilogue scale/shift
    if (tid < BN) {
        int cc = colOff + tid;
        if constexpr (EPI == 1) {
            scS[tid] = 1.f; shS[tid] = bias[cc];
        } else if constexpr (EPI == 2) {
            float sc = gm[cc] * rsqrtf(vr[cc] + BN_EPS);
            scS[tid] = sc;
            shS[tid] = (bias[cc] - mn[cc]) * sc + bt[cc];
        } else {
            scS[tid] = 1.f; shS[tid] = 0.f;
        }
    }

    // W slab [FIN x BN] fp32 -> fp16 smem (once)
    for (int idx = tid; idx < FIN * (BN / 4); idx += 256) {
        int k = idx / (BN / 4), c4 = idx % (BN / 4);
        float4 v = *reinterpret_cast<const float4*>(
            &W[(size_t)k * FOUT + colOff + c4 * 4]);
        uint2 st;
        st.x = h2u(__floats2half2_rn(v.x, v.y));
        st.y = h2u(__floats2half2_rn(v.z, v.w));
        *reinterpret_cast<uint2*>(&sm.l.Ws[k][c4 * 4]) = st;
    }
    __syncthreads();

    wmma::fragment<wmma::accumulator, 16, 16, 16, float> cf[BN / 16];
    #pragma unroll
    for (int i = 0; i < BN / 16; i++) wmma::fill_fragment(cf[i], 0.f);

    for (int k0 = 0; k0 < FIN; k0 += 16) {
        // A tile [BM x 16] -> fp16 smem (2 threads per row)
        {
            int row = tid >> 1;
            int ch = (tid & 1) * 8;
            int grow = rowBase + row;
            uint4 st = make_uint4(0u, 0u, 0u, 0u);
            if (grow < n) {
                if constexpr (AH) {
                    const __half* A = (const __half*)Av;
                    st = *reinterpret_cast<const uint4*>(
                        &A[(size_t)grow * FIN + k0 + ch]);
                } else {
                    const float* A = (const float*)Av;
                    float4 v0 = *reinterpret_cast<const float4*>(
                        &A[(size_t)grow * FIN + k0 + ch]);
                    float4 v1 = *reinterpret_cast<const float4*>(
                        &A[(size_t)grow * FIN + k0 + ch + 4]);
                    st.x = h2u(__floats2half2_rn(v0.x, v0.y));
                    st.y = h2u(__floats2half2_rn(v0.z, v0.w));
                    st.z = h2u(__floats2half2_rn(v1.x, v1.y));
                    st.w = h2u(__floats2half2_rn(v1.z, v1.w));
                }
            }
            *reinterpret_cast<uint4*>(&sm.l.As[row][ch]) = st;
        }
        __syncthreads();

        wmma::fragment<wmma::matrix_a, 16, 16, 16, __half, wmma::row_major> af;
        wmma::load_matrix_sync(af, &sm.l.As[warp * 16][0], ALD);
        #pragma unroll
        for (int nf = 0; nf < BN / 16; nf++) {
            wmma::fragment<wmma::matrix_b, 16, 16, 16, __half, wmma::row_major> bf;
            wmma::load_matrix_sync(bf, &sm.l.Ws[k0][nf * 16], WLD);
            wmma::mma_sync(cf[nf], af, bf, cf[nf]);
        }
        __syncthreads();
    }

    // accumulators -> smem (overlay; loop buffers dead after last sync)
    #pragma unroll
    for (int nf = 0; nf < BN / 16; nf++)
        wmma::store_matrix_sync(&sm.Cs[warp * 16][nf * 16], cf[nf], CLD,
                                wmma::mem_row_major);
    __syncthreads();

    // epilogue: scale/shift (+relu), fp16 store
    for (int idx = tid; idx < BM * (BN / 4); idx += 256) {
        int row = idx / (BN / 4), c4 = idx % (BN / 4);
        int grow = rowBase + row;
        if (grow >= n) continue;
        float4 v = *reinterpret_cast<float4*>(&sm.Cs[row][c4 * 4]);
        int c = c4 * 4;
        float v0 = v.x * scS[c]     + shS[c];
        float v1 = v.y * scS[c + 1] + shS[c + 1];
        float v2 = v.z * scS[c + 2] + shS[c + 2];
        float v3 = v.w * scS[c + 3] + shS[c + 3];
        if constexpr (EPI != 0) {
            v0 = fmaxf(v0, 0.f); v1 = fmaxf(v1, 0.f);
            v2 = fmaxf(v2, 0.f); v3 = fmaxf(v3, 0.f);
        }
        uint2 st;
        st.x = h2u(__floats2half2_rn(v0, v1));
        st.y = h2u(__floats2half2_rn(v2, v3));
        *reinterpret_cast<uint2*>(&C[(size_t)grow * FOUT + colOff + c]) = st;
    }
}

template <int FIN, int FOUT, int EPI, bool AH>
__global__ __launch_bounds__(256) void k_gemm(
    const void* __restrict__ A, const float* __restrict__ W,
    const float* __restrict__ bias,
    const float* __restrict__ gm, const float* __restrict__ bt,
    const float* __restrict__ mn, const float* __restrict__ vr,
    __half* __restrict__ C, int n)
{
    gemm_hmma_body<FIN, FOUT, EPI, AH>(A, W, bias, gm, bt, mn, vr, C, n,
                                       blockIdx.x, blockIdx.y);
}

// fused: blocks [0, gbE) scatter edges (half2 weights); rest run gemm0 (HMMA).
__global__ __launch_bounds__(256) void k_fill_gemm0(
    int E, int gbE,
    const float* __restrict__ x, const float* __restrict__ w_in,
    const float* __restrict__ b_in, __half* __restrict__ h0, int n)
{
    if ((int)blockIdx.x < gbE) {
        int e = blockIdx.x * blockDim.x + threadIdx.x;
        if (e >= E) return;
        int s = g_src[e], d = g_dstA[e];
        int pos = atomicAdd(&g_cursor[d], 1);
        float w = g_dinv[s] * g_dinv[d];
        unsigned int wh = h2u(__floats2half2_rn(w, w));
        g_edge[pos] = ((unsigned long long)wh << 32) |
                      (unsigned long long)(unsigned int)s;
    } else {
        gemm_hmma_body<128, 64, 1, false>(x, w_in, b_in, nullptr, nullptr,
                                          nullptr, nullptr, h0, n,
                                          (int)blockIdx.x - gbE, 0);
    }
}

// ---------------- aggregation: O[i] = sum_e w[e]*H[col[e]] -------------------
// fp16 storage, HFMA2 accumulation, 4 independent edge streams per node
// (row split in quarters) -> MLP ~8 loads/thread, hides L2 latency.
// 8 feats/thread via LDG.128; TPN = FW/8 threads per node; 256-thread blocks.
// EPI 0: store half sums. EPI 2 (FW=64): bn+relu, fused (h @ w_out + b_out)
//        -> log_softmax (fp32 out); also re-zeroes g_deg (last kernel of call).
template <int FW, int EPI>
__global__ __launch_bounds__(256) void k_agg(
    const __half* __restrict__ H, __half* __restrict__ O,
    const float* __restrict__ b,
    const float* __restrict__ gm, const float* __restrict__ bt,
    const float* __restrict__ mn, const float* __restrict__ vr,
    const float* __restrict__ Wo, const float* __restrict__ bo,
    float* __restrict__ out, int n)
{
    constexpr int TPN = FW / 8;            // threads per node (8 or 16)
    constexpr int NPB = 256 / TPN;         // nodes per block  (32 or 16)

    __shared__ float wsT[8 * 64];          // [c][f]   (EPI==2 only)
    __shared__ float bsh[8];
    __shared__ float scS[64], shS[64];     // bn scale/shift (EPI==2)
    int tidF = threadIdx.y * TPN + threadIdx.x;
    if constexpr (EPI == 2) {
        for (int idx = tidF; idx < 512; idx += 256) {
            int f = idx >> 3, c = idx & 7;
            wsT[c * 64 + f] = Wo[idx];
        }
        if (tidF < 8) bsh[tidF] = bo[tidF];
        if (tidF < 64) {
            float sc = gm[tidF] * rsqrtf(vr[tidF] + BN_EPS);
            scS[tidF] = sc;
            shS[tidF] = (b[tidF] - mn[tidF]) * sc + bt[tidF];
        }
        // cleanup for next call: restore g_deg == 0 invariant
        if (tidF < NPB) {
            int z = blockIdx.x * NPB + tidF;
            if (z < n) g_deg[z] = 0;
        }
        __syncthreads();
    }

    int node = blockIdx.x * NPB + threadIdx.y;
    if (node >= n) return;
    int f8 = threadIdx.x;                  // feature-octet index
    const __half* Hq = H + 8 * f8;

    int s = g_rowptr[node], e = g_rowptr[node + 1];
    int len = e - s;
    int q = (len + 3) >> 2;                // stream length

    __half2 acc[4][4];
    #pragma unroll
    for (int k = 0; k < 4; k++)
        #pragma unroll
        for (int j = 0; j < 4; j++) acc[k][j] = __float2half2_rn(0.f);

    for (int j = 0; j < q; j++) {
        unsigned long long ed[4];
        bool ok[4];
        #pragma unroll
        for (int k = 0; k < 4; k++) {
            int idx = k * q + j;
            ok[k] = (idx < len);
            ed[k] = ok[k] ? g_edge[s + idx] : 0ull;
        }
        uint4 v[4];
        #pragma unroll
        for (int k = 0; k < 4; k++) {
            if (ok[k])
                v[k] = *reinterpret_cast<const uint4*>(
                    &Hq[(size_t)(unsigned int)ed[k] * FW]);
        }
        #pragma unroll
        for (int k = 0; k < 4; k++) {
            if (ok[k]) {
                __half2 w = u2h((unsigned int)(ed[k] >> 32));
                acc[k][0] = __hfma2(w, u2h(v[k].x), acc[k][0]);
                acc[k][1] = __hfma2(w, u2h(v[k].y), acc[k][1]);
                acc[k][2] = __hfma2(w, u2h(v[k].z), acc[k][2]);
                acc[k][3] = __hfma2(w, u2h(v[k].w), acc[k][3]);
            }
        }
    }

    // combine streams in fp32
    float fa[8];
    #pragma unroll
    for (int j = 0; j < 4; j++) {
        float2 t0 = __half22float2(acc[0][j]);
        float2 t1 = __half22float2(acc[1][j]);
        float2 t2 = __half22float2(acc[2][j]);
        float2 t3 = __half22float2(acc[3][j]);
        fa[2 * j]     = (t0.x + t1.x) + (t2.x + t3.x);
        fa[2 * j + 1] = (t0.y + t1.y) + (t2.y + t3.y);
    }

    int f = 8 * f8;
    if constexpr (EPI == 2) {
        // bn + relu on 8 feats (smem-precomputed scale/shift)
        float v[8];
        #pragma unroll
        for (int c = 0; c < 8; c++)
            v[c] = fmaxf(fa[c] * scS[f + c] + shS[f + c], 0.f);
        // fused 64x8 GEMM: reduce over 8 lanes of this node subgroup
        float l[8];
        #pragma unroll
        for (int c = 0; c < 8; c++) {
            float pr = 0.f;
            #pragma unroll
            for (int j = 0; j < 8; j++)
                pr = fmaf(v[j], wsT[c * 64 + f + j], pr);
            #pragma unroll
            for (int off = 4; off; off >>= 1)
                pr += __shfl_xor_sync(0xffffffff, pr, off);
            l[c] = pr + bsh[c];
        }
        float mx = l[0];
        #pragma unroll
        for (int c = 1; c < 8; c++) mx = fmaxf(mx, l[c]);
        float se = 0.f;
        #pragma unroll
        for (int c = 0; c < 8; c++) se += expf(l[c] - mx);
        float lse = mx + logf(se);
        float myl = l[0];
        #pragma unroll
        for (int c = 1; c < 8; c++) myl = (f8 == c) ? l[c] : myl;
        out[(size_t)node * 8 + f8] = myl - lse;
    } else {
        uint4 st;
        st.x = h2u(__floats2half2_rn(fa[0], fa[1]));
        st.y = h2u(__floats2half2_rn(fa[2], fa[3]));
        st.z = h2u(__floats2half2_rn(fa[4], fa[5]));
        st.w = h2u(__floats2half2_rn(fa[6], fa[7]));
        *reinterpret_cast<uint4*>(&O[(size_t)node * FW + f]) = st;
    }
}

// ---------------- host ----------------
extern "C" void kernel_launch(void* const* d_in, const int* in_sizes, int n_in,
                              void* d_out, int out_size)
{
    int n = in_sizes[0] / 128;     // x: [N,128]
    int E = in_sizes[1] / 2;       // edge_index: [2,E]

    bool dictOrder = in_sizes[6] > 512;

    const float* x    = (const float*)d_in[0];
    const void*  eidx = d_in[1];
    const float* w_in = (const float*)d_in[2];
    const float* b_in = (const float*)d_in[3];
    const float* w1   = (const float*)d_in[4];
    const float* b1   = (const float*)d_in[5];
    const float *w2, *b2, *w3, *b3, *w_out, *b_out;
    const float *G1, *BE1, *M1, *V1, *G2, *BE2, *M2, *V2, *G3, *BE3, *M3, *V3;
    if (dictOrder) {
        w2 = (const float*)d_in[6];  b2 = (const float*)d_in[7];
        w3 = (const float*)d_in[8];  b3 = (const float*)d_in[9];
        w_out = (const float*)d_in[10]; b_out = (const float*)d_in[11];
        G1 = (const float*)d_in[12]; BE1 = (const float*)d_in[13];
        M1 = (const float*)d_in[14]; V1  = (const float*)d_in[15];
        G2 = (const float*)d_in[16]; BE2 = (const float*)d_in[17];
        M2 = (const float*)d_in[18]; V2  = (const float*)d_in[19];
        G3 = (const float*)d_in[20]; BE3 = (const float*)d_in[21];
        M3 = (const float*)d_in[22]; V3  = (const float*)d_in[23];
    } else {
        G1 = (const float*)d_in[6];  BE1 = (const float*)d_in[7];
        M1 = (const float*)d_in[8];  V1  = (const float*)d_in[9];
        w2 = (const float*)d_in[10]; b2  = (const float*)d_in[11];
        G2 = (const float*)d_in[12]; BE2 = (const float*)d_in[13];
        M2 = (const float*)d_in[14]; V2  = (const float*)d_in[15];
        w3 = (const float*)d_in[16]; b3  = (const float*)d_in[17];
        G3 = (const float*)d_in[18]; BE3 = (const float*)d_in[19];
        M3 = (const float*)d_in[20]; V3  = (const float*)d_in[21];
        w_out = (const float*)d_in[22]; b_out = (const float*)d_in[23];
    }

    __half *h0p, *tp, *hp;
    cudaGetSymbolAddress((void**)&h0p, g_h0);
    cudaGetSymbolAddress((void**)&tp,  g_t);
    cudaGetSymbolAddress((void**)&hp,  g_h);

    const int TB = 256;
    int gbE = (E + TB - 1) / TB;
    int gbG = (n + 127) / 128;      // BM=128 for all HMMA gemms

    // idx 0: convert + stage + degree count (g_deg zeroed by prior call / load)
    k_convert_count<<<gbE, TB>>>(eidx, E);
    // idx 1: scan + dinv + cursor + self-loops
    k_scan_node<<<1, 1024>>>(n);
    // idx 2: fused edge scatter + gemm0: h0 = relu(x @ w_in + b_in)   [N,64]
    k_fill_gemm0<<<gbE + gbG, TB>>>(E, gbE, x, w_in, b_in, h0p, n);
    // idx 3 (PROFILED): t1 = A @ h0                                   [N,64]
    {
        dim3 blk(8, 32);
        k_agg<64, 0><<<(n + 31) / 32, blk>>>(h0p, tp, nullptr, nullptr, nullptr,
                                             nullptr, nullptr, nullptr, nullptr,
                                             nullptr, n);
    }
    // h1 = relu(bn1(t1 @ w1 + b1))                                    [N,128]
    k_gemm<64, 128, 2, true><<<dim3(gbG, 2), 256>>>(tp, w1, b1, G1, BE1, M1, V1,
                                                    hp, n);
    // t2 = A @ h1                                                     [N,128]
    {
        dim3 blk(16, 16);
        k_agg<128, 0><<<(n + 15) / 16, blk>>>(hp, tp, nullptr, nullptr, nullptr,
                                              nullptr, nullptr, nullptr, nullptr,
                                              nullptr, n);
    }
    // h2 = relu(bn2(t2 @ w2 + b2))                                    [N,128]
    k_gemm<128, 128, 2, true><<<dim3(gbG, 2), 256>>>(tp, w2, b2, G2, BE2, M2, V2,
                                                     hp, n);
    // t3 = h2 @ w3                                                    [N,64]
    k_gemm<128, 64, 0, true><<<gbG, 256>>>(hp, w3, nullptr, nullptr, nullptr,
                                           nullptr, nullptr, tp, n);
    // fused final: h3 = relu(bn3(A @ t3 + b3));
    //              out = log_softmax(h3 @ w_out + b_out)  (+ g_deg cleanup)
    {
        dim3 blk(8, 32);
        k_agg<64, 2><<<(n + 31) / 32, blk>>>(tp, nullptr, b3, G3, BE3, M3, V3,
                                             w_out, b_out, (float*)d_out, n);
    }
}

// round 17
// speedup vs baseline: 1.4185x; 1.0088x over previous
#include <cuda_runtime.h>
#include <cuda_fp16.h>
#include <mma.h>
#include <math.h>

using namespace nvcuda;

#define NMAX 100000
#define EMAX 1600000
#define BN_EPS 1e-5f

// ---------------- device scratch (zero-initialized at module load) ----------
__device__ int   g_src[EMAX];
__device__ int   g_dstA[EMAX];
__device__ int   g_deg[NMAX];          // invariant: all-zero at entry of each call
__device__ float g_dinv[NMAX];
__device__ int   g_rowptr[NMAX + 1];
__device__ int   g_cursor[NMAX];
// edge word: low32 = col byte-offset for 64-feat fp16 row (col << 7),
//            high32 = half2{w, w}
__device__ unsigned long long g_edge[EMAX + NMAX];
__device__ __align__(16) __half g_h0[(size_t)NMAX * 64];
__device__ __align__(16) __half g_t [(size_t)NMAX * 128];
__device__ __align__(16) __half g_h [(size_t)NMAX * 128];

// ---------------- packed helpers ----------------
__device__ __forceinline__ unsigned int h2u(__half2 h) {
    return *reinterpret_cast<unsigned int*>(&h);
}
__device__ __forceinline__ __half2 u2h(unsigned int u) {
    return *reinterpret_cast<__half2*>(&u);
}

// ---------------- preprocessing ----------------

// convert to int32 src/dst (staged) + count in-degree; int64-vs-int32 detected
// per block from the first 64 words (identical data -> identical answer).
__global__ __launch_bounds__(256) void k_convert_count(const void* eidx, int E) {
    __shared__ int sIs64;
    {
        int lane = threadIdx.x & 31;
        if (threadIdx.x < 32) {
            const unsigned int* p = (const unsigned int*)eidx;
            unsigned int ok = (p[2 * lane + 1] == 0u);
            unsigned int bal = __ballot_sync(0xffffffff, ok);
            if (lane == 0) sIs64 = (bal == 0xffffffffu);
        }
    }
    __syncthreads();
    int i = blockIdx.x * blockDim.x + threadIdx.x;
    if (i >= E) return;
    int s, d;
    if (sIs64) {
        const long long* p = (const long long*)eidx;
        s = (int)p[i];
        d = (int)p[(size_t)E + i];
    } else {
        const int* p = (const int*)eidx;
        s = p[i];
        d = p[E + i];
    }
    g_src[i] = s;
    g_dstA[i] = d;
    atomicAdd(&g_deg[d], 1);
}

// single-block: exclusive scan of (deg[i]+1) -> rowptr, plus per-node work:
// dinv, cursor init, self-loop (half2 weight, byte-offset col) in last slot.
__global__ void k_scan_node(int n) {
    __shared__ int s[1024];
    int t = threadIdx.x;
    int chunk = (n + 1023) / 1024;
    int lo = t * chunk;
    int hi = lo + chunk; if (hi > n) hi = n;
    int sum = 0;
    if (lo < n) for (int i = lo; i < hi; i++) sum += g_deg[i] + 1;
    s[t] = sum;
    __syncthreads();
    for (int d = 1; d < 1024; d <<= 1) {
        int v = 0;
        if (t >= d) v = s[t - d];
        __syncthreads();
        s[t] += v;
        __syncthreads();
    }
    int off = (t == 0) ? 0 : s[t - 1];
    if (lo < n) {
        int run = off;
        for (int i = lo; i < hi; i++) {
            int deg = g_deg[i];
            g_rowptr[i] = run;
            g_cursor[i] = run;
            float di = rsqrtf((float)(deg + 1));
            g_dinv[i] = di;
            float w = di * di;
            unsigned int wh = h2u(__floats2half2_rn(w, w));
            g_edge[run + deg] = ((unsigned long long)wh << 32) |
                                (unsigned long long)((unsigned int)i << 7);
            run += deg + 1;
        }
    }
    if (t == 1023) g_rowptr[n] = s[1023];
}

// scatter edges into CSR slots (byte-offset col, half2 weight)
__global__ __launch_bounds__(256) void k_fill(int E) {
    int e = blockIdx.x * blockDim.x + threadIdx.x;
    if (e >= E) return;
    int s = g_src[e], d = g_dstA[e];
    int pos = atomicAdd(&g_cursor[d], 1);
    float w = g_dinv[s] * g_dinv[d];
    unsigned int wh = h2u(__floats2half2_rn(w, w));
    g_edge[pos] = ((unsigned long long)wh << 32) |
                  (unsigned long long)((unsigned int)s << 7);
}

// ---------------- HMMA GEMM: C[n,FOUT] = A[n,FIN] @ W[FIN,FOUT] -------------
// fp16 inputs (W converted in-kernel), fp32 accumulate, fp16 store.
// BM=128 x BN=64 per block; FOUT=128 handled by gridDim.y == 2.
// EPI: 0 = none, 1 = bias+relu, 2 = bias+bn+relu
template <int FIN, int FOUT, int EPI, bool AH>
__device__ __forceinline__ void gemm_hmma_body(
    const void* __restrict__ Av, const float* __restrict__ W,
    const float* __restrict__ bias,
    const float* __restrict__ gm, const float* __restrict__ bt,
    const float* __restrict__ mn, const float* __restrict__ vr,
    __half* __restrict__ C, int n, int bid, int ny)
{
    constexpr int BM = 128, BN = 64;
    constexpr int WLD = BN + 8;      // 72 halves per Ws row
    constexpr int ALD = 24;          // 16 + 8 halves per As row
    constexpr int CLD = BN + 4;      // 68 floats per Cs row

    union SmemU {
        struct { __half Ws[FIN][WLD]; __half As[BM][ALD]; } l;
        float Cs[BM][CLD];
    };
    __shared__ SmemU sm;
    __shared__ float scS[BN], shS[BN];

    int tid = threadIdx.x;
    int warp = tid >> 5;
    int rowBase = bid * BM;
    int colOff = ny * BN;

    // per-column epilogue scale/shift
    if (tid < BN) {
        int cc = colOff + tid;
        if constexpr (EPI == 1) {
            scS[tid] = 1.f; shS[tid] = bias[cc];
        } else if constexpr (EPI == 2) {
            float sc = gm[cc] * rsqrtf(vr[cc] + BN_EPS);
            scS[tid] = sc;
            shS[tid] = (bias[cc] - mn[cc]) * sc + bt[cc];
        } else {
            scS[tid] = 1.f; shS[tid] = 0.f;
        }
    }

    // W slab [FIN x BN] fp32 -> fp16 smem (once)
    for (int idx = tid; idx < FIN * (BN / 4); idx += 256) {
        int k = idx / (BN / 4), c4 = idx % (BN / 4);
        float4 v = *reinterpret_cast<const float4*>(
            &W[(size_t)k * FOUT + colOff + c4 * 4]);
        uint2 st;
        st.x = h2u(__floats2half2_rn(v.x, v.y));
        st.y = h2u(__floats2half2_rn(v.z, v.w));
        *reinterpret_cast<uint2*>(&sm.l.Ws[k][c4 * 4]) = st;
    }
    __syncthreads();

    wmma::fragment<wmma::accumulator, 16, 16, 16, float> cf[BN / 16];
    #pragma unroll
    for (int i = 0; i < BN / 16; i++) wmma::fill_fragment(cf[i], 0.f);

    for (int k0 = 0; k0 < FIN; k0 += 16) {
        // A tile [BM x 16] -> fp16 smem (2 threads per row)
        {
            int row = tid >> 1;
            int ch = (tid & 1) * 8;
            int grow = rowBase + row;
            uint4 st = make_uint4(0u, 0u, 0u, 0u);
            if (grow < n) {
                if constexpr (AH) {
                    const __half* A = (const __half*)Av;
                    st = *reinterpret_cast<const uint4*>(
                        &A[(size_t)grow * FIN + k0 + ch]);
                } else {
                    const float* A = (const float*)Av;
                    float4 v0 = *reinterpret_cast<const float4*>(
                        &A[(size_t)grow * FIN + k0 + ch]);
                    float4 v1 = *reinterpret_cast<const float4*>(
                        &A[(size_t)grow * FIN + k0 + ch + 4]);
                    st.x = h2u(__floats2half2_rn(v0.x, v0.y));
                    st.y = h2u(__floats2half2_rn(v0.z, v0.w));
                    st.z = h2u(__floats2half2_rn(v1.x, v1.y));
                    st.w = h2u(__floats2half2_rn(v1.z, v1.w));
                }
            }
            *reinterpret_cast<uint4*>(&sm.l.As[row][ch]) = st;
        }
        __syncthreads();

        wmma::fragment<wmma::matrix_a, 16, 16, 16, __half, wmma::row_major> af;
        wmma::load_matrix_sync(af, &sm.l.As[warp * 16][0], ALD);
        #pragma unroll
        for (int nf = 0; nf < BN / 16; nf++) {
            wmma::fragment<wmma::matrix_b, 16, 16, 16, __half, wmma::row_major> bf;
            wmma::load_matrix_sync(bf, &sm.l.Ws[k0][nf * 16], WLD);
            wmma::mma_sync(cf[nf], af, bf, cf[nf]);
        }
        __syncthreads();
    }

    // accumulators -> smem (overlay; loop buffers dead after last sync)
    #pragma unroll
    for (int nf = 0; nf < BN / 16; nf++)
        wmma::store_matrix_sync(&sm.Cs[warp * 16][nf * 16], cf[nf], CLD,
                                wmma::mem_row_major);
    __syncthreads();

    // epilogue: scale/shift (+relu), fp16 store
    for (int idx = tid; idx < BM * (BN / 4); idx += 256) {
        int row = idx / (BN / 4), c4 = idx % (BN / 4);
        int grow = rowBase + row;
        if (grow >= n) continue;
        float4 v = *reinterpret_cast<float4*>(&sm.Cs[row][c4 * 4]);
        int c = c4 * 4;
        float v0 = v.x * scS[c]     + shS[c];
        float v1 = v.y * scS[c + 1] + shS[c + 1];
        float v2 = v.z * scS[c + 2] + shS[c + 2];
        float v3 = v.w * scS[c + 3] + shS[c + 3];
        if constexpr (EPI != 0) {
            v0 = fmaxf(v0, 0.f); v1 = fmaxf(v1, 0.f);
            v2 = fmaxf(v2, 0.f); v3 = fmaxf(v3, 0.f);
        }
        uint2 st;
        st.x = h2u(__floats2half2_rn(v0, v1));
        st.y = h2u(__floats2half2_rn(v2, v3));
        *reinterpret_cast<uint2*>(&C[(size_t)grow * FOUT + colOff + c]) = st;
    }
}

template <int FIN, int FOUT, int EPI, bool AH>
__global__ __launch_bounds__(256) void k_gemm(
    const void* __restrict__ A, const float* __restrict__ W,
    const float* __restrict__ bias,
    const float* __restrict__ gm, const float* __restrict__ bt,
    const float* __restrict__ mn, const float* __restrict__ vr,
    __half* __restrict__ C, int n)
{
    gemm_hmma_body<FIN, FOUT, EPI, AH>(A, W, bias, gm, bt, mn, vr, C, n,
                                       blockIdx.x, blockIdx.y);
}

// ---------------- aggregation: O[i] = sum_e w[e]*H[col[e]] -------------------
// fp16 storage, HFMA2 accumulation, 4 independent edge streams per node.
// Edge low32 is a BYTE OFFSET for 64-feat rows; FW=128 shifts left by 1
// (LEA instead of wide IMAD per gather).
// 8 feats/thread via LDG.128; TPN = FW/8 threads per node; 256-thread blocks.
// EPI 0: store half sums. EPI 2 (FW=64): bn+relu, fused (h @ w_out + b_out)
//        -> log_softmax (fp32 out); also re-zeroes g_deg (last kernel of call).
template <int FW, int EPI>
__global__ __launch_bounds__(256) void k_agg(
    const __half* __restrict__ H, __half* __restrict__ O,
    const float* __restrict__ b,
    const float* __restrict__ gm, const float* __restrict__ bt,
    const float* __restrict__ mn, const float* __restrict__ vr,
    const float* __restrict__ Wo, const float* __restrict__ bo,
    float* __restrict__ out, int n)
{
    constexpr int TPN = FW / 8;            // threads per node (8 or 16)
    constexpr int NPB = 256 / TPN;         // nodes per block  (32 or 16)
    constexpr int SH  = (FW == 128) ? 1 : 0;

    __shared__ float wsT[8 * 64];          // [c][f]   (EPI==2 only)
    __shared__ float bsh[8];
    __shared__ float scS[64], shS[64];     // bn scale/shift (EPI==2)
    int tidF = threadIdx.y * TPN + threadIdx.x;
    if constexpr (EPI == 2) {
        for (int idx = tidF; idx < 512; idx += 256) {
            int f = idx >> 3, c = idx & 7;
            wsT[c * 64 + f] = Wo[idx];
        }
        if (tidF < 8) bsh[tidF] = bo[tidF];
        if (tidF < 64) {
            float sc = gm[tidF] * rsqrtf(vr[tidF] + BN_EPS);
            scS[tidF] = sc;
            shS[tidF] = (b[tidF] - mn[tidF]) * sc + bt[tidF];
        }
        // cleanup for next call: restore g_deg == 0 invariant
        if (tidF < NPB) {
            int z = blockIdx.x * NPB + tidF;
            if (z < n) g_deg[z] = 0;
        }
        __syncthreads();
    }

    int node = blockIdx.x * NPB + threadIdx.y;
    if (node >= n) return;
    int f8 = threadIdx.x;                  // feature-octet index
    const char* Hb = (const char*)(H + 8 * f8);

    int s = g_rowptr[node], e = g_rowptr[node + 1];
    int len = e - s;
    int q = (len + 3) >> 2;                // stream length

    __half2 acc[4][4];
    #pragma unroll
    for (int k = 0; k < 4; k++)
        #pragma unroll
        for (int j = 0; j < 4; j++) acc[k][j] = __float2half2_rn(0.f);

    for (int j = 0; j < q; j++) {
        unsigned long long ed[4];
        bool ok[4];
        #pragma unroll
        for (int k = 0; k < 4; k++) {
            int idx = k * q + j;
            ok[k] = (idx < len);
            ed[k] = ok[k] ? g_edge[s + idx] : 0ull;
        }
        uint4 v[4];
        #pragma unroll
        for (int k = 0; k < 4; k++) {
            if (ok[k])
                v[k] = *reinterpret_cast<const uint4*>(
                    Hb + ((size_t)(unsigned int)ed[k] << SH));
        }
        #pragma unroll
        for (int k = 0; k < 4; k++) {
            if (ok[k]) {
                __half2 w = u2h((unsigned int)(ed[k] >> 32));
                acc[k][0] = __hfma2(w, u2h(v[k].x), acc[k][0]);
                acc[k][1] = __hfma2(w, u2h(v[k].y), acc[k][1]);
                acc[k][2] = __hfma2(w, u2h(v[k].z), acc[k][2]);
                acc[k][3] = __hfma2(w, u2h(v[k].w), acc[k][3]);
            }
        }
    }

    // combine streams in fp32
    float fa[8];
    #pragma unroll
    for (int j = 0; j < 4; j++) {
        float2 t0 = __half22float2(acc[0][j]);
        float2 t1 = __half22float2(acc[1][j]);
        float2 t2 = __half22float2(acc[2][j]);
        float2 t3 = __half22float2(acc[3][j]);
        fa[2 * j]     = (t0.x + t1.x) + (t2.x + t3.x);
        fa[2 * j + 1] = (t0.y + t1.y) + (t2.y + t3.y);
    }

    int f = 8 * f8;
    if constexpr (EPI == 2) {
        // bn + relu on 8 feats (smem-precomputed scale/shift)
        float v[8];
        #pragma unroll
        for (int c = 0; c < 8; c++)
            v[c] = fmaxf(fa[c] * scS[f + c] + shS[f + c], 0.f);
        // fused 64x8 GEMM: reduce over 8 lanes of this node subgroup
        float l[8];
        #pragma unroll
        for (int c = 0; c < 8; c++) {
            float pr = 0.f;
            #pragma unroll
            for (int j = 0; j < 8; j++)
                pr = fmaf(v[j], wsT[c * 64 + f + j], pr);
            #pragma unroll
            for (int off = 4; off; off >>= 1)
                pr += __shfl_xor_sync(0xffffffff, pr, off);
            l[c] = pr + bsh[c];
        }
        float mx = l[0];
        #pragma unroll
        for (int c = 1; c < 8; c++) mx = fmaxf(mx, l[c]);
        float se = 0.f;
        #pragma unroll
        for (int c = 0; c < 8; c++) se += expf(l[c] - mx);
        float lse = mx + logf(se);
        float myl = l[0];
        #pragma unroll
        for (int c = 1; c < 8; c++) myl = (f8 == c) ? l[c] : myl;
        out[(size_t)node * 8 + f8] = myl - lse;
    } else {
        uint4 st;
        st.x = h2u(__floats2half2_rn(fa[0], fa[1]));
        st.y = h2u(__floats2half2_rn(fa[2], fa[3]));
        st.z = h2u(__floats2half2_rn(fa[4], fa[5]));
        st.w = h2u(__floats2half2_rn(fa[6], fa[7]));
        *reinterpret_cast<uint4*>(&O[(size_t)node * FW + f]) = st;
    }
}

// ---------------- host ----------------
extern "C" void kernel_launch(void* const* d_in, const int* in_sizes, int n_in,
                              void* d_out, int out_size)
{
    int n = in_sizes[0] / 128;     // x: [N,128]
    int E = in_sizes[1] / 2;       // edge_index: [2,E]

    bool dictOrder = in_sizes[6] > 512;

    const float* x    = (const float*)d_in[0];
    const void*  eidx = d_in[1];
    const float* w_in = (const float*)d_in[2];
    const float* b_in = (const float*)d_in[3];
    const float* w1   = (const float*)d_in[4];
    const float* b1   = (const float*)d_in[5];
    const float *w2, *b2, *w3, *b3, *w_out, *b_out;
    const float *G1, *BE1, *M1, *V1, *G2, *BE2, *M2, *V2, *G3, *BE3, *M3, *V3;
    if (dictOrder) {
        w2 = (const float*)d_in[6];  b2 = (const float*)d_in[7];
        w3 = (const float*)d_in[8];  b3 = (const float*)d_in[9];
        w_out = (const float*)d_in[10]; b_out = (const float*)d_in[11];
        G1 = (const float*)d_in[12]; BE1 = (const float*)d_in[13];
        M1 = (const float*)d_in[14]; V1  = (const float*)d_in[15];
        G2 = (const float*)d_in[16]; BE2 = (const float*)d_in[17];
        M2 = (const float*)d_in[18]; V2  = (const float*)d_in[19];
        G3 = (const float*)d_in[20]; BE3 = (const float*)d_in[21];
        M3 = (const float*)d_in[22]; V3  = (const float*)d_in[23];
    } else {
        G1 = (const float*)d_in[6];  BE1 = (const float*)d_in[7];
        M1 = (const float*)d_in[8];  V1  = (const float*)d_in[9];
        w2 = (const float*)d_in[10]; b2  = (const float*)d_in[11];
        G2 = (const float*)d_in[12]; BE2 = (const float*)d_in[13];
        M2 = (const float*)d_in[14]; V2  = (const float*)d_in[15];
        w3 = (const float*)d_in[16]; b3  = (const float*)d_in[17];
        G3 = (const float*)d_in[18]; BE3 = (const float*)d_in[19];
        M3 = (const float*)d_in[20]; V3  = (const float*)d_in[21];
        w_out = (const float*)d_in[22]; b_out = (const float*)d_in[23];
    }

    __half *h0p, *tp, *hp;
    cudaGetSymbolAddress((void**)&h0p, g_h0);
    cudaGetSymbolAddress((void**)&tp,  g_t);
    cudaGetSymbolAddress((void**)&hp,  g_h);

    const int TB = 256;
    int gbE = (E + TB - 1) / TB;
    int gbG = (n + 127) / 128;      // BM=128 for all HMMA gemms

    // idx 0: convert + stage + degree count (g_deg zeroed by prior call / load)
    k_convert_count<<<gbE, TB>>>(eidx, E);
    // idx 1: scan + dinv + cursor + self-loops
    k_scan_node<<<1, 1024>>>(n);
    // idx 2: edge scatter into CSR
    k_fill<<<gbE, TB>>>(E);
    // idx 3 (PROFILED): gemm0: h0 = relu(x @ w_in + b_in)             [N,64]
    k_gemm<128, 64, 1, false><<<gbG, 256>>>(x, w_in, b_in, nullptr, nullptr,
                                            nullptr, nullptr, h0p, n);
    // t1 = A @ h0                                                     [N,64]
    {
        dim3 blk(8, 32);
        k_agg<64, 0><<<(n + 31) / 32, blk>>>(h0p, tp, nullptr, nullptr, nullptr,
                                             nullptr, nullptr, nullptr, nullptr,
                                             nullptr, n);
    }
    // h1 = relu(bn1(t1 @ w1 + b1))                                    [N,128]
    k_gemm<64, 128, 2, true><<<dim3(gbG, 2), 256>>>(tp, w1, b1, G1, BE1, M1, V1,
                                                    hp, n);
    // t2 = A @ h1                                                     [N,128]
    {
        dim3 blk(16, 16);
        k_agg<128, 0><<<(n + 15) / 16, blk>>>(hp, tp, nullptr, nullptr, nullptr,
                                              nullptr, nullptr, nullptr, nullptr,
                                              nullptr, n);
    }
    // h2 = relu(bn2(t2 @ w2 + b2))                                    [N,128]
    k_gemm<128, 128, 2, true><<<dim3(gbG, 2), 256>>>(tp, w2, b2, G2, BE2, M2, V2,
                                                     hp, n);
    // t3 = h2 @ w3                                                    [N,64]
    k_gemm<128, 64, 0, true><<<gbG, 256>>>(hp, w3, nullptr, nullptr, nullptr,
                                           nullptr, nullptr, tp, n);
    // fused final: h3 = relu(bn3(A @ t3 + b3));
    //              out = log_softmax(h3 @ w_out + b_out)  (+ g_deg cleanup)
    {
        dim3 blk(8, 32);
        k_agg<64, 2><<<(n + 31) / 32, blk>>>(tp, nullptr, b3, G3, BE3, M3, V3,
                                             w_out, b_out, (float*)d_out, n);
    }
}